// round 4
// baseline (speedup 1.0000x reference)
#include <cuda_runtime.h>
#include <cuda_bf16.h>
#include <cstdint>

#define BATCH 8
#define CCH   256
#define SPA   16384
#define HEADS 2
#define HK    128

// ---------------- scratch ----------------
__device__ float g_mean[CCH];
__device__ float g_rstd[CCH];
__device__ float g_wf[768 * 256];
__device__ float g_bf[768];
__device__ float g_k[BATCH * CCH * SPA];
__device__ float g_q[BATCH * CCH * SPA];
__device__ float g_v[BATCH * CCH * SPA];
__device__ float g_ctx_part[16 * 16 * 128 * 128];
__device__ float g_context[16 * 128 * 128];
__device__ float g_ctx[BATCH * 128 * 128];
__device__ float g_pooled[16];
__device__ float g_gate[16];
__device__ float g_kmax[2048];
__device__ float g_kinv[2048];
__device__ float g_qm[BATCH * 2 * SPA];
__device__ float g_qinv[BATCH * 2 * SPA];
__device__ float g_M[BATCH * 256 * 256];
__device__ float g_b2[256];

// ---------------- tf32 helpers ----------------
__device__ __forceinline__ uint32_t f2tf32(float f) {
    uint32_t r;
    asm("cvt.rna.tf32.f32 %0, %1;" : "=r"(r) : "f"(f));
    return r;
}

__device__ __forceinline__ void mma_tf32(float c[4], const uint32_t a[4], const uint32_t b[2]) {
    asm volatile(
        "mma.sync.aligned.m16n8k8.row.col.f32.tf32.tf32.f32 "
        "{%0,%1,%2,%3}, {%4,%5,%6,%7}, {%8,%9}, {%0,%1,%2,%3};"
        : "+f"(c[0]), "+f"(c[1]), "+f"(c[2]), "+f"(c[3])
        : "r"(a[0]), "r"(a[1]), "r"(a[2]), "r"(a[3]), "r"(b[0]), "r"(b[1]));
}

// ======== fragment-ready staging (Kstage = 16, tiles 128x128) ========
// Af: [ksl(2)][mt(8)][lane(32)][v(4)]  = 2048 words / stage
// Bf: [ksl(2)][nt(16)][lane(32)][v(2)] = 2048 words / stage

// A: thread handles row=tid>>1, k-offset (tid&1)*8, 2x float4
__device__ __forceinline__ void stageA(uint32_t* Af, int tid, const float4* pa) {
    const int row = tid >> 1, ksl = tid & 1;
    const int mt = row >> 4, g = row & 7, rh = (row >> 3) & 1;
    uint32_t* base = Af + (((ksl * 8 + mt) * 32 + g * 4) << 2) + rh;
#pragma unroll
    for (int f = 0; f < 2; ++f) {
        base[0  + 2 * f] = f2tf32(pa[f].x);
        base[4  + 2 * f] = f2tf32(pa[f].y);
        base[8  + 2 * f] = f2tf32(pa[f].z);
        base[12 + 2 * f] = f2tf32(pa[f].w);
    }
}

__device__ __forceinline__ void stageA_exp(uint32_t* Af, int tid, const float4* pa,
                                           float km, float kiv) {
    const int row = tid >> 1, ksl = tid & 1;
    const int mt = row >> 4, g = row & 7, rh = (row >> 3) & 1;
    uint32_t* base = Af + (((ksl * 8 + mt) * 32 + g * 4) << 2) + rh;
#pragma unroll
    for (int f = 0; f < 2; ++f) {
        base[0  + 2 * f] = f2tf32(__expf(pa[f].x - km) * kiv);
        base[4  + 2 * f] = f2tf32(__expf(pa[f].y - km) * kiv);
        base[8  + 2 * f] = f2tf32(__expf(pa[f].z - km) * kiv);
        base[12 + 2 * f] = f2tf32(__expf(pa[f].w - km) * kiv);
    }
}

// B k-major source: thread handles k=tid>>4, n-offset (tid&15)*8, 2x float4
__device__ __forceinline__ void stageB_kmaj(uint32_t* Bf, int tid, const float4* pb) {
    const int k = tid >> 4, nt = tid & 15;
    const int ksl = k >> 3, tig = k & 3, v = (k >> 2) & 1;
    uint32_t* base = Bf + (((ksl * 16 + nt) * 32 + tig) << 1) + v;
#pragma unroll
    for (int f = 0; f < 2; ++f) {
        base[32 * f + 0]  = f2tf32(pb[f].x);
        base[32 * f + 8]  = f2tf32(pb[f].y);
        base[32 * f + 16] = f2tf32(pb[f].z);
        base[32 * f + 24] = f2tf32(pb[f].w);
    }
}

__device__ __forceinline__ void stageB_kmaj_exp(uint32_t* Bf, int tid, const float4* pb,
                                                const float4* mv, const float4* iv) {
    const int k = tid >> 4, nt = tid & 15;
    const int ksl = k >> 3, tig = k & 3, v = (k >> 2) & 1;
    uint32_t* base = Bf + (((ksl * 16 + nt) * 32 + tig) << 1) + v;
#pragma unroll
    for (int f = 0; f < 2; ++f) {
        base[32 * f + 0]  = f2tf32(__expf(pb[f].x - mv[f].x) * iv[f].x);
        base[32 * f + 8]  = f2tf32(__expf(pb[f].y - mv[f].y) * iv[f].y);
        base[32 * f + 16] = f2tf32(__expf(pb[f].z - mv[f].z) * iv[f].z);
        base[32 * f + 24] = f2tf32(__expf(pb[f].w - mv[f].w) * iv[f].w);
    }
}

// B n-major source (transposed stage): thread handles n=tid>>1, k-offset (tid&1)*8
__device__ __forceinline__ void stageB_nmaj(uint32_t* Bf, int tid, const float4* pb) {
    const int n = tid >> 1, ksl = tid & 1;
    uint32_t* base = Bf + (((ksl * 16 + (n >> 3)) * 32 + (n & 7) * 4) << 1);
#pragma unroll
    for (int f = 0; f < 2; ++f) {
        base[0 + f] = f2tf32(pb[f].x);
        base[2 + f] = f2tf32(pb[f].y);
        base[4 + f] = f2tf32(pb[f].z);
        base[6 + f] = f2tf32(pb[f].w);
    }
}

// compute one staged K=16 slice: 32 MMAs per warp
__device__ __forceinline__ void compute_stage(const uint32_t* Af, const uint32_t* Bf,
                                              int mtb, int ntb, int lane,
                                              float (&acc)[4][4][4]) {
#pragma unroll
    for (int ksl = 0; ksl < 2; ++ksl) {
        uint32_t a[4][4], b[4][2];
        const uint32_t* Ab = Af + (((ksl * 8 + mtb) * 32 + lane) << 2);
        const uint32_t* Bb = Bf + (((ksl * 16 + ntb) * 32 + lane) << 1);
#pragma unroll
        for (int i = 0; i < 4; ++i) {
            uint4 t = *(const uint4*)(Ab + (i << 7));
            a[i][0] = t.x; a[i][1] = t.y; a[i][2] = t.z; a[i][3] = t.w;
        }
#pragma unroll
        for (int j = 0; j < 4; ++j) {
            uint2 t = *(const uint2*)(Bb + (j << 6));
            b[j][0] = t.x; b[j][1] = t.y;
        }
#pragma unroll
        for (int i = 0; i < 4; ++i)
#pragma unroll
            for (int j = 0; j < 4; ++j)
                mma_tf32(acc[i][j], a[i], b[j]);
    }
}

// ---------------- K1: BatchNorm statistics ----------------
__global__ void k_bnstats(const float* __restrict__ x) {
    const int c = blockIdx.x;
    const int tid = threadIdx.x;
    float s = 0.f, s2 = 0.f;
    for (int b = 0; b < BATCH; ++b) {
        const float4* p = (const float4*)(x + ((size_t)(b * CCH + c) << 14));
        for (int i = tid; i < SPA / 4; i += 256) {
            float4 v = p[i];
            s  += v.x + v.y + v.z + v.w;
            s2 += v.x * v.x + v.y * v.y + v.z * v.z + v.w * v.w;
        }
    }
    __shared__ float sa[256], sb[256];
    sa[tid] = s; sb[tid] = s2;
    __syncthreads();
    for (int st = 128; st > 0; st >>= 1) {
        if (tid < st) { sa[tid] += sa[tid + st]; sb[tid] += sb[tid + st]; }
        __syncthreads();
    }
    if (tid == 0) {
        const float inv_n = 1.f / (float)(BATCH * SPA);
        float mean = sa[0] * inv_n;
        float var  = sb[0] * inv_n - mean * mean;
        g_mean[c] = mean;
        g_rstd[c] = rsqrtf(var + 1e-5f);
    }
}

// ---------------- K2: fold BN into kqv weights ----------------
__global__ void k_fuseW(const float* __restrict__ wk, const float* __restrict__ bk,
                        const float* __restrict__ wq, const float* __restrict__ bq,
                        const float* __restrict__ wv, const float* __restrict__ bv,
                        const float* __restrict__ gamma, const float* __restrict__ beta) {
    int o = blockIdx.x * blockDim.x + threadIdx.x;
    if (o >= 768) return;
    const float* W; const float* bias; int r;
    if (o < 256)      { W = wk; bias = bk; r = o; }
    else if (o < 512) { W = wq; bias = bq; r = o - 256; }
    else              { W = wv; bias = bv; r = o - 512; }
    float bacc = bias[r];
    for (int c = 0; c < 256; ++c) {
        float a = g_rstd[c] * gamma[c];
        float d = beta[c] - g_mean[c] * a;
        float w = W[r * 256 + c];
        g_wf[o * 256 + c] = w * a;
        bacc += w * d;
    }
    g_bf[o] = bacc;
}

// ---------------- K3: fused kqv GEMM (pipelined tf32) ----------------
__global__ __launch_bounds__(256) void k_gemm_kqv(const float* __restrict__ x) {
    __shared__ uint32_t Af[2][2048];
    __shared__ uint32_t Bf[2][2048];
    const int tid = threadIdx.x;
    const int lane = tid & 31, wid = tid >> 5;
    const int g = lane >> 2, tig = lane & 3;
    const int mtb = (wid & 1) * 4, ntb = (wid >> 1) * 4;
    const int mw = (wid & 1) * 64, nw = (wid >> 1) * 32;

    const int m0 = blockIdx.x << 7;
    const int by = blockIdx.y;
    const int b = by >> 7, s0 = (by & 127) << 7;
    const float* Bbase = x + ((size_t)b * CCH) * SPA;

    const int ar = tid >> 1, koffA = (tid & 1) * 8;
    const int bk = tid >> 4, bs = (tid & 15) * 8;

    float4 na[2], nb[2];
    float acc[4][4][4] = {};

#pragma unroll
    for (int f = 0; f < 2; ++f) {
        na[f] = *(const float4*)(g_wf + (m0 + ar) * 256 + koffA + f * 4);
        nb[f] = *(const float4*)(Bbase + (size_t)bk * SPA + s0 + bs + f * 4);
    }
    stageA(Af[0], tid, na);
    stageB_kmaj(Bf[0], tid, nb);
#pragma unroll
    for (int f = 0; f < 2; ++f) {
        na[f] = *(const float4*)(g_wf + (m0 + ar) * 256 + 16 + koffA + f * 4);
        nb[f] = *(const float4*)(Bbase + (size_t)(16 + bk) * SPA + s0 + bs + f * 4);
    }
    __syncthreads();

    for (int it = 0; it < 16; ++it) {
        const int cur = it & 1;
        if (it + 1 < 16) { stageA(Af[cur ^ 1], tid, na); stageB_kmaj(Bf[cur ^ 1], tid, nb); }
        if (it + 2 < 16) {
            const int ks = (it + 2) * 16;
#pragma unroll
            for (int f = 0; f < 2; ++f) {
                na[f] = *(const float4*)(g_wf + (m0 + ar) * 256 + ks + koffA + f * 4);
                nb[f] = *(const float4*)(Bbase + (size_t)(ks + bk) * SPA + s0 + bs + f * 4);
            }
        }
        compute_stage(Af[cur], Bf[cur], mtb, ntb, lane, acc);
        __syncthreads();
    }

    float* dst; int rbase;
    if (m0 < 256)      { dst = g_k; rbase = m0; }
    else if (m0 < 512) { dst = g_q; rbase = m0 - 256; }
    else               { dst = g_v; rbase = m0 - 512; }

#pragma unroll
    for (int i = 0; i < 4; ++i) {
        int row0 = mw + i * 16 + g;
        float bias0 = g_bf[m0 + row0];
        float bias1 = g_bf[m0 + row0 + 8];
#pragma unroll
        for (int j = 0; j < 4; ++j) {
            int col = s0 + nw + j * 8 + tig * 2;
            float* o0 = dst + (size_t)(b * CCH + rbase + row0) * SPA + col;
            float* o1 = o0 + 8 * SPA;
            *(float2*)o0 = make_float2(acc[i][j][0] + bias0, acc[i][j][1] + bias0);
            *(float2*)o1 = make_float2(acc[i][j][2] + bias1, acc[i][j][3] + bias1);
        }
    }
}

// ---------------- K4: k row stats ----------------
__global__ __launch_bounds__(256) void k_kstats() {
    const size_t base = (size_t)blockIdx.x << 14;
    const float4* p = (const float4*)(g_k + base);
    const int tid = threadIdx.x;
    float4 v[16];
    float m = -1e30f;
#pragma unroll
    for (int i = 0; i < 16; ++i) {
        v[i] = p[tid + (i << 8)];
        m = fmaxf(m, fmaxf(fmaxf(v[i].x, v[i].y), fmaxf(v[i].z, v[i].w)));
    }
    __shared__ float sm[256];
    sm[tid] = m; __syncthreads();
    for (int st = 128; st > 0; st >>= 1) {
        if (tid < st) sm[tid] = fmaxf(sm[tid], sm[tid + st]);
        __syncthreads();
    }
    const float rowm = sm[0];
    __syncthreads();
    float l = 0.f;
#pragma unroll
    for (int i = 0; i < 16; ++i)
        l += __expf(v[i].x - rowm) + __expf(v[i].y - rowm)
           + __expf(v[i].z - rowm) + __expf(v[i].w - rowm);
    sm[tid] = l; __syncthreads();
    for (int st = 128; st > 0; st >>= 1) {
        if (tid < st) sm[tid] += sm[tid + st];
        __syncthreads();
    }
    if (tid == 0) {
        g_kmax[blockIdx.x] = rowm;
        g_kinv[blockIdx.x] = 1.f / sm[0];
    }
}

// ---------------- K5: q column stats ----------------
__global__ void k_qstats() {
    int j = blockIdx.x * 256 + threadIdx.x;
    int b = j >> 15;
    int n = (j >> 14) & 1;
    int s = j & 16383;
    const float* col = g_q + ((size_t)(b * CCH + n * HK)) * SPA + s;
    float m = -1e30f, l = 0.f;
    for (int kc = 0; kc < HK; ++kc) {
        float xv = col[(size_t)kc * SPA];
        float nm = fmaxf(m, xv);
        l = l * __expf(m - nm) + __expf(xv - nm);
        m = nm;
    }
    g_qm[j]   = m;
    g_qinv[j] = 1.f / l;
}

// ---------------- K6: context partials softmax(k) @ v^T (pipelined) ----------
__global__ __launch_bounds__(256) void k_context() {
    __shared__ uint32_t Af[2][2048];
    __shared__ uint32_t Bf[2][2048];
    const int tid = threadIdx.x;
    const int lane = tid & 31, wid = tid >> 5;
    const int g = lane >> 2, tig = lane & 3;
    const int mtb = (wid & 1) * 4, ntb = (wid >> 1) * 4;
    const int mw = (wid & 1) * 64, nw = (wid >> 1) * 32;

    const int split = blockIdx.x;
    const int bn = blockIdx.y;
    const float* Kb = g_k + ((size_t)bn * HK) * SPA;
    const float* Vb = g_v + ((size_t)bn * HK) * SPA;
    const int sb0 = split * 1024;

    const int row = tid >> 1, soff = (tid & 1) * 8;
    const float km  = g_kmax[bn * HK + row];
    const float kiv = g_kinv[bn * HK + row];

    float4 na[2], nb[2];
    float acc[4][4][4] = {};

#pragma unroll
    for (int f = 0; f < 2; ++f) {
        na[f] = *(const float4*)(Kb + (size_t)row * SPA + sb0 + soff + f * 4);
        nb[f] = *(const float4*)(Vb + (size_t)row * SPA + sb0 + soff + f * 4);
    }
    stageA_exp(Af[0], tid, na, km, kiv);
    stageB_nmaj(Bf[0], tid, nb);
#pragma unroll
    for (int f = 0; f < 2; ++f) {
        na[f] = *(const float4*)(Kb + (size_t)row * SPA + sb0 + 16 + soff + f * 4);
        nb[f] = *(const float4*)(Vb + (size_t)row * SPA + sb0 + 16 + soff + f * 4);
    }
    __syncthreads();

    for (int it = 0; it < 64; ++it) {
        const int cur = it & 1;
        if (it + 1 < 64) { stageA_exp(Af[cur ^ 1], tid, na, km, kiv); stageB_nmaj(Bf[cur ^ 1], tid, nb); }
        if (it + 2 < 64) {
            const int ks = (it + 2) * 16;
#pragma unroll
            for (int f = 0; f < 2; ++f) {
                na[f] = *(const float4*)(Kb + (size_t)row * SPA + sb0 + ks + soff + f * 4);
                nb[f] = *(const float4*)(Vb + (size_t)row * SPA + sb0 + ks + soff + f * 4);
            }
        }
        compute_stage(Af[cur], Bf[cur], mtb, ntb, lane, acc);
        __syncthreads();
    }

    float* outp = g_ctx_part + ((size_t)(bn * 16 + split)) * 16384;
#pragma unroll
    for (int i = 0; i < 4; ++i) {
        int row0 = mw + i * 16 + g;
#pragma unroll
        for (int j = 0; j < 4; ++j) {
            int col = nw + j * 8 + tig * 2;
            float* o0 = outp + row0 * 128 + col;
            float* o1 = o0 + 8 * 128;
            *(float2*)o0 = make_float2(acc[i][j][0], acc[i][j][1]);
            *(float2*)o1 = make_float2(acc[i][j][2], acc[i][j][3]);
        }
    }
}

// ---------------- K7: reduce partials + pooled mean ----------------
__global__ void k_reduce_ctx() {
    const int bn = blockIdx.x;
    const int tid = threadIdx.x;
    float acc = 0.f;
    for (int e = tid; e < 16384; e += 256) {
        float s = 0.f;
#pragma unroll
        for (int p = 0; p < 16; ++p)
            s += g_ctx_part[((size_t)(bn * 16 + p)) * 16384 + e];
        g_context[((size_t)bn << 14) + e] = s;
        acc += s;
    }
    __shared__ float sm[256];
    sm[tid] = acc; __syncthreads();
    for (int st = 128; st > 0; st >>= 1) {
        if (tid < st) sm[tid] += sm[tid + st];
        __syncthreads();
    }
    if (tid == 0) g_pooled[bn] = sm[0] * (1.f / 16384.f);
}

// ---------------- K8: SE gate ----------------
__global__ void k_gate(const float* __restrict__ w_fc1, const float* __restrict__ b_fc1,
                       const float* __restrict__ w_fc2, const float* __restrict__ b_fc2) {
    int b = threadIdx.x;
    if (b >= BATCH) return;
    float p0 = g_pooled[b * 2], p1 = g_pooled[b * 2 + 1];
    float h0 = fmaxf(0.f, p0 * w_fc1[0] + p1 * w_fc1[1] + b_fc1[0]);
    float h1 = fmaxf(0.f, p0 * w_fc1[2] + p1 * w_fc1[3] + b_fc1[1]);
    float z0 = h0 * w_fc2[0] + h1 * w_fc2[1] + b_fc2[0];
    float z1 = h0 * w_fc2[2] + h1 * w_fc2[3] + b_fc2[1];
    g_gate[b * 2]     = 1.f / (1.f + __expf(-z0));
    g_gate[b * 2 + 1] = 1.f / (1.f + __expf(-z1));
}

// ---------------- K9: combine heads ----------------
__global__ void k_combine(const float* __restrict__ w_se) {
    int idx = blockIdx.x * 256 + threadIdx.x;
    int b = idx >> 14;
    int e = idx & 16383;
    float v = w_se[0] * g_gate[b * 2]     * g_context[((size_t)(b * 2))     * 16384 + e]
            + w_se[1] * g_gate[b * 2 + 1] * g_context[((size_t)(b * 2 + 1)) * 16384 + e];
    g_ctx[idx] = v;
}

// ---------------- K10: M_b = w_rep-slices @ ctx_b ----------------
__global__ __launch_bounds__(256) void k_mkM(const float* __restrict__ w_rep) {
    __shared__ float Ws[64][65];
    __shared__ float Cs[64][65];
    const int bid = blockIdx.x;
    const int b = bid >> 4;
    const int rem = bid & 15;
    const int ot = rem >> 2, kt = rem & 3;
    const int n = kt >> 1;
    const int kc0 = (kt & 1) << 6;
    const int o0 = ot << 6;
    const int tid = threadIdx.x;
    const int tx = tid & 15, ty = tid >> 4;
    const float* ctxb = g_ctx + (size_t)b * 16384;
    float acc[4][4] = {};
    const int lrow = tid >> 2;
    const int lc0 = (tid & 3) << 4;
    for (int h = 0; h < 2; ++h) {
        const int vb = n * 128 + h * 64;
#pragma unroll
        for (int f = 0; f < 4; ++f) {
            float4 wv = *(const float4*)(w_rep + (o0 + lrow) * 256 + vb + lc0 + f * 4);
            Ws[lrow][lc0 + f * 4 + 0] = wv.x; Ws[lrow][lc0 + f * 4 + 1] = wv.y;
            Ws[lrow][lc0 + f * 4 + 2] = wv.z; Ws[lrow][lc0 + f * 4 + 3] = wv.w;
            float4 cv = *(const float4*)(ctxb + (kc0 + lrow) * 128 + h * 64 + lc0 + f * 4);
            Cs[lrow][lc0 + f * 4 + 0] = cv.x; Cs[lrow][lc0 + f * 4 + 1] = cv.y;
            Cs[lrow][lc0 + f * 4 + 2] = cv.z; Cs[lrow][lc0 + f * 4 + 3] = cv.w;
        }
        __syncthreads();
        for (int vl = 0; vl < 64; ++vl) {
            float a[4], bb[4];
#pragma unroll
            for (int i = 0; i < 4; ++i) a[i]  = Ws[ty * 4 + i][vl];
#pragma unroll
            for (int j = 0; j < 4; ++j) bb[j] = Cs[tx * 4 + j][vl];
#pragma unroll
            for (int i = 0; i < 4; ++i)
#pragma unroll
                for (int j = 0; j < 4; ++j) acc[i][j] += a[i] * bb[j];
        }
        __syncthreads();
    }
#pragma unroll
    for (int i = 0; i < 4; ++i)
#pragma unroll
        for (int j = 0; j < 4; ++j)
            g_M[(size_t)b * 65536 + (o0 + ty * 4 + i) * 256 + kt * 64 + tx * 4 + j] = acc[i][j];
}

// ---------------- K11: b2 bias fold ----------------
__global__ void k_bias2(const float* __restrict__ w_rep, const float* __restrict__ b_rep,
                        const float* __restrict__ b_se) {
    int o = threadIdx.x;
    float s = 0.f;
    for (int c = 0; c < 256; ++c) s += w_rep[o * 256 + c];
    g_b2[o] = b_rep[o] + b_se[0] * s;
}

// ---------------- K12: fused final GEMM (pipelined, exp in staging) ----------
__global__ __launch_bounds__(256) void k_final_fused(float* __restrict__ out) {
    __shared__ uint32_t Af[2][2048];
    __shared__ uint32_t Bf[2][2048];
    const int tid = threadIdx.x;
    const int lane = tid & 31, wid = tid >> 5;
    const int g = lane >> 2, tig = lane & 3;
    const int mtb = (wid & 1) * 4, ntb = (wid >> 1) * 4;
    const int mw = (wid & 1) * 64, nw = (wid >> 1) * 32;

    const int m0 = blockIdx.x << 7;
    const int by = blockIdx.y;
    const int b = by >> 7, s0 = (by & 127) << 7;
    const float* Am = g_M + (size_t)b * 65536;
    const float* Bq = g_q + (size_t)b * CCH * SPA;
    const float* qm = g_qm   + ((size_t)(b * 2) << 14);
    const float* qi = g_qinv + ((size_t)(b * 2) << 14);

    const int ar = tid >> 1, koffA = (tid & 1) * 8;
    const int bk = tid >> 4, bs = (tid & 15) * 8;

    float4 na[2], nb[2], mv[2], iv[2];
    float acc[4][4][4] = {};

#pragma unroll
    for (int f = 0; f < 2; ++f) {
        na[f] = *(const float4*)(Am + (m0 + ar) * 256 + koffA + f * 4);
        nb[f] = *(const float4*)(Bq + (size_t)bk * SPA + s0 + bs + f * 4);
        mv[f] = *(const float4*)(qm + s0 + bs + f * 4);
        iv[f] = *(const float4*)(qi + s0 + bs + f * 4);
    }
    stageA(Af[0], tid, na);
    stageB_kmaj_exp(Bf[0], tid, nb, mv, iv);
#pragma unroll
    for (int f = 0; f < 2; ++f) {
        na[f] = *(const float4*)(Am + (m0 + ar) * 256 + 16 + koffA + f * 4);
        nb[f] = *(const float4*)(Bq + (size_t)(16 + bk) * SPA + s0 + bs + f * 4);
        // head of rows 16..31 is still 0; mv/iv unchanged
    }
    __syncthreads();

    for (int it = 0; it < 16; ++it) {
        const int cur = it & 1;
        if (it + 1 < 16) { stageA(Af[cur ^ 1], tid, na); stageB_kmaj_exp(Bf[cur ^ 1], tid, nb, mv, iv); }
        if (it + 2 < 16) {
            const int ks = (it + 2) * 16;
            const int nbh = (ks >> 7) << 14;   // head select
#pragma unroll
            for (int f = 0; f < 2; ++f) {
                na[f] = *(const float4*)(Am + (m0 + ar) * 256 + ks + koffA + f * 4);
                nb[f] = *(const float4*)(Bq + (size_t)(ks + bk) * SPA + s0 + bs + f * 4);
                mv[f] = *(const float4*)(qm + nbh + s0 + bs + f * 4);
                iv[f] = *(const float4*)(qi + nbh + s0 + bs + f * 4);
            }
        }
        compute_stage(Af[cur], Bf[cur], mtb, ntb, lane, acc);
        __syncthreads();
    }

#pragma unroll
    for (int i = 0; i < 4; ++i) {
        int row0 = m0 + mw + i * 16 + g;
        float bias0 = g_b2[row0];
        float bias1 = g_b2[row0 + 8];
#pragma unroll
        for (int j = 0; j < 4; ++j) {
            int col = s0 + nw + j * 8 + tig * 2;
            float* o0 = out + (size_t)(b * CCH + row0) * SPA + col;
            float* o1 = o0 + (size_t)8 * SPA;
            *(float2*)o0 = make_float2(acc[i][j][0] + bias0, acc[i][j][1] + bias0);
            *(float2*)o1 = make_float2(acc[i][j][2] + bias1, acc[i][j][3] + bias1);
        }
    }
}

// ---------------- launch ----------------
extern "C" void kernel_launch(void* const* d_in, const int* in_sizes, int n_in,
                              void* d_out, int out_size) {
    const float* x     = (const float*)d_in[0];
    const float* gamma = (const float*)d_in[1];
    const float* beta  = (const float*)d_in[2];
    const float* wk    = (const float*)d_in[3];
    const float* bk    = (const float*)d_in[4];
    const float* wq    = (const float*)d_in[5];
    const float* bq    = (const float*)d_in[6];
    const float* wv    = (const float*)d_in[7];
    const float* bv    = (const float*)d_in[8];
    const float* w_fc1 = (const float*)d_in[9];
    const float* b_fc1 = (const float*)d_in[10];
    const float* w_fc2 = (const float*)d_in[11];
    const float* b_fc2 = (const float*)d_in[12];
    const float* w_se  = (const float*)d_in[13];
    const float* b_se  = (const float*)d_in[14];
    const float* w_rep = (const float*)d_in[15];
    const float* b_rep = (const float*)d_in[16];
    float* out = (float*)d_out;

    k_bnstats<<<256, 256>>>(x);
    k_fuseW<<<3, 256>>>(wk, bk, wq, bq, wv, bv, gamma, beta);
    k_gemm_kqv<<<dim3(6, 1024), 256>>>(x);
    k_kstats<<<2048, 256>>>();
    k_qstats<<<1024, 256>>>();
    k_context<<<dim3(16, 16), 256>>>();
    k_reduce_ctx<<<16, 256>>>();
    k_gate<<<1, 32>>>(w_fc1, b_fc1, w_fc2, b_fc2);
    k_combine<<<512, 256>>>(w_se);
    k_mkM<<<128, 256>>>(w_rep);
    k_bias2<<<1, 256>>>(w_rep, b_rep, b_se);
    k_final_fused<<<dim3(2, 1024), 256>>>(out);
}

// round 6
// speedup vs baseline: 1.9652x; 1.9652x over previous
#include <cuda_runtime.h>
#include <cuda_fp16.h>
#include <cstdint>

#define BATCH 8
#define CCH   256
#define SPA   16384
#define HEADS 2
#define HK    128

// ---------------- scratch ----------------
__device__ float g_mean[CCH];
__device__ float g_rstd[CCH];
__device__ float g_wf[768 * 256];
__device__ float g_bf[768];
__device__ float g_k[BATCH * CCH * SPA];
__device__ float g_q[BATCH * CCH * SPA];
__device__ float g_v[BATCH * CCH * SPA];
__device__ float g_ctx_part[16 * 16 * 128 * 128];
__device__ float g_context[16 * 128 * 128];
__device__ float g_ctx[BATCH * 128 * 128];
__device__ float g_pooled[16];
__device__ float g_gate[16];
__device__ float g_kmax[2048];
__device__ float g_kinv[2048];
__device__ float g_qm[BATCH * 2 * SPA];
__device__ float g_qinv[BATCH * 2 * SPA];
__device__ float g_M[BATCH * 256 * 256];
__device__ float g_b2[256];

#define CTX_SCALE      16384.0f
#define CTX_UNSCALE    (1.0f / 16384.0f)

// ---------------- fp16 mma helpers ----------------
__device__ __forceinline__ uint32_t pk2(float lo, float hi) {
    uint32_t r;
    asm("cvt.rn.f16x2.f32 %0, %1, %2;" : "=r"(r) : "f"(hi), "f"(lo));
    return r;
}

__device__ __forceinline__ void mma_f16(float c[4], const uint32_t a[4], const uint32_t b[2]) {
    asm volatile(
        "mma.sync.aligned.m16n8k16.row.col.f32.f16.f16.f32 "
        "{%0,%1,%2,%3}, {%4,%5,%6,%7}, {%8,%9}, {%0,%1,%2,%3};"
        : "+f"(c[0]), "+f"(c[1]), "+f"(c[2]), "+f"(c[3])
        : "r"(a[0]), "r"(a[1]), "r"(a[2]), "r"(a[3]), "r"(b[0]), "r"(b[1]));
}

// smem layouts (half2 words). Staging block = 32 k-floats = 16 half2 rows.
// As: [row 0..127][kpair 0..15], stride 20 (conflict-free fragment loads)
// Bs: [kpair 0..15][col 0..127], stride 136 (8 mod 32 -> conflict-free)
#define AS_H 20
#define BS_H 136

// one staged 32-k block: 2 x (16 MMA m16n8k16) per warp
__device__ __forceinline__ void mma_block16(const uint32_t* __restrict__ As,
                                            const uint32_t* __restrict__ Bs,
                                            int mw, int nw, int g, int tig,
                                            float (&acc)[4][4][4]) {
#pragma unroll
    for (int ks2 = 0; ks2 < 16; ks2 += 8) {
        uint32_t a[4][4], b[4][2];
#pragma unroll
        for (int i = 0; i < 4; ++i) {
            const uint32_t* A0 = As + (mw + i * 16 + g) * AS_H + ks2;
            const uint32_t* A1 = A0 + 8 * AS_H;
            a[i][0] = A0[tig];     a[i][1] = A1[tig];
            a[i][2] = A0[tig + 4]; a[i][3] = A1[tig + 4];
        }
#pragma unroll
        for (int j = 0; j < 4; ++j) {
            int cb = nw + j * 8 + g;
            b[j][0] = Bs[(ks2 + tig) * BS_H + cb];
            b[j][1] = Bs[(ks2 + tig + 4) * BS_H + cb];
        }
#pragma unroll
        for (int i = 0; i < 4; ++i)
#pragma unroll
            for (int j = 0; j < 4; ++j)
                mma_f16(acc[i][j], a[i], b[j]);
    }
}

// ---------------- K1: BatchNorm statistics ----------------
__global__ void k_bnstats(const float* __restrict__ x) {
    const int c = blockIdx.x;
    const int tid = threadIdx.x;
    float s = 0.f, s2 = 0.f;
    for (int b = 0; b < BATCH; ++b) {
        const float4* p = (const float4*)(x + ((size_t)(b * CCH + c) << 14));
        for (int i = tid; i < SPA / 4; i += 256) {
            float4 v = p[i];
            s  += v.x + v.y + v.z + v.w;
            s2 += v.x * v.x + v.y * v.y + v.z * v.z + v.w * v.w;
        }
    }
    __shared__ float sa[256], sb[256];
    sa[tid] = s; sb[tid] = s2;
    __syncthreads();
    for (int st = 128; st > 0; st >>= 1) {
        if (tid < st) { sa[tid] += sa[tid + st]; sb[tid] += sb[tid + st]; }
        __syncthreads();
    }
    if (tid == 0) {
        const float inv_n = 1.f / (float)(BATCH * SPA);
        float mean = sa[0] * inv_n;
        float var  = sb[0] * inv_n - mean * mean;
        g_mean[c] = mean;
        g_rstd[c] = rsqrtf(var + 1e-5f);
    }
}

// ---------------- K2: fold BN into kqv weights ----------------
__global__ void k_fuseW(const float* __restrict__ wk, const float* __restrict__ bk,
                        const float* __restrict__ wq, const float* __restrict__ bq,
                        const float* __restrict__ wv, const float* __restrict__ bv,
                        const float* __restrict__ gamma, const float* __restrict__ beta) {
    int o = blockIdx.x * blockDim.x + threadIdx.x;
    if (o >= 768) return;
    const float* W; const float* bias; int r;
    if (o < 256)      { W = wk; bias = bk; r = o; }
    else if (o < 512) { W = wq; bias = bq; r = o - 256; }
    else              { W = wv; bias = bv; r = o - 512; }
    float bacc = bias[r];
    for (int c = 0; c < 256; ++c) {
        float a = g_rstd[c] * gamma[c];
        float d = beta[c] - g_mean[c] * a;
        float w = W[r * 256 + c];
        g_wf[o * 256 + c] = w * a;
        bacc += w * d;
    }
    g_bf[o] = bacc;
}

// ---------------- K3: fused kqv GEMM (fp16 m16n8k16) ----------------
__global__ __launch_bounds__(256) void k_gemm_kqv(const float* __restrict__ x) {
    __shared__ uint32_t As[128 * AS_H];
    __shared__ uint32_t Bs[16 * BS_H];
    const int tid = threadIdx.x;
    const int lane = tid & 31, wid = tid >> 5;
    const int g = lane >> 2, tig = lane & 3;
    const int mw = (wid & 1) * 64, nw = (wid >> 1) * 32;

    const int m0 = blockIdx.x << 7;
    const int by = blockIdx.y;
    const int b = by >> 7, s0 = (by & 127) << 7;
    const float* Bbase = x + ((size_t)b * CCH) * SPA;

    const int ar = tid >> 1, ak = (tid & 1) * 16;       // A: row, k-offset
    const int bkp = tid >> 4, bs = (tid & 15) * 8;      // B: k-pair, s-offset

    float4 pa[4], pb[4];
    float acc[4][4][4] = {};

    // stage block 0
#pragma unroll
    for (int f = 0; f < 4; ++f)
        pa[f] = *(const float4*)(g_wf + (m0 + ar) * 256 + ak + f * 4);
    {
        const float* r0 = Bbase + (size_t)(2 * bkp) * SPA + s0 + bs;
        pb[0] = *(const float4*)r0;  pb[1] = *(const float4*)(r0 + 4);
        pb[2] = *(const float4*)(r0 + SPA); pb[3] = *(const float4*)(r0 + SPA + 4);
    }
    {
        uint32_t* dA = As + ar * AS_H + (ak >> 1);
        dA[0] = pk2(pa[0].x, pa[0].y); dA[1] = pk2(pa[0].z, pa[0].w);
        dA[2] = pk2(pa[1].x, pa[1].y); dA[3] = pk2(pa[1].z, pa[1].w);
        dA[4] = pk2(pa[2].x, pa[2].y); dA[5] = pk2(pa[2].z, pa[2].w);
        dA[6] = pk2(pa[3].x, pa[3].y); dA[7] = pk2(pa[3].z, pa[3].w);
        uint32_t* dB = Bs + bkp * BS_H + bs;
        dB[0] = pk2(pb[0].x, pb[2].x); dB[1] = pk2(pb[0].y, pb[2].y);
        dB[2] = pk2(pb[0].z, pb[2].z); dB[3] = pk2(pb[0].w, pb[2].w);
        dB[4] = pk2(pb[1].x, pb[3].x); dB[5] = pk2(pb[1].y, pb[3].y);
        dB[6] = pk2(pb[1].z, pb[3].z); dB[7] = pk2(pb[1].w, pb[3].w);
    }
    __syncthreads();

    for (int it = 0; it < 8; ++it) {
        const bool more = (it + 1) < 8;
        if (more) {
            const int ks = (it + 1) * 32;
#pragma unroll
            for (int f = 0; f < 4; ++f)
                pa[f] = *(const float4*)(g_wf + (m0 + ar) * 256 + ks + ak + f * 4);
            const float* r0 = Bbase + (size_t)(ks + 2 * bkp) * SPA + s0 + bs;
            pb[0] = *(const float4*)r0;  pb[1] = *(const float4*)(r0 + 4);
            pb[2] = *(const float4*)(r0 + SPA); pb[3] = *(const float4*)(r0 + SPA + 4);
        }
        mma_block16(As, Bs, mw, nw, g, tig, acc);
        __syncthreads();
        if (more) {
            uint32_t* dA = As + ar * AS_H + (ak >> 1);
            dA[0] = pk2(pa[0].x, pa[0].y); dA[1] = pk2(pa[0].z, pa[0].w);
            dA[2] = pk2(pa[1].x, pa[1].y); dA[3] = pk2(pa[1].z, pa[1].w);
            dA[4] = pk2(pa[2].x, pa[2].y); dA[5] = pk2(pa[2].z, pa[2].w);
            dA[6] = pk2(pa[3].x, pa[3].y); dA[7] = pk2(pa[3].z, pa[3].w);
            uint32_t* dB = Bs + bkp * BS_H + bs;
            dB[0] = pk2(pb[0].x, pb[2].x); dB[1] = pk2(pb[0].y, pb[2].y);
            dB[2] = pk2(pb[0].z, pb[2].z); dB[3] = pk2(pb[0].w, pb[2].w);
            dB[4] = pk2(pb[1].x, pb[3].x); dB[5] = pk2(pb[1].y, pb[3].y);
            dB[6] = pk2(pb[1].z, pb[3].z); dB[7] = pk2(pb[1].w, pb[3].w);
            __syncthreads();
        }
    }

    float* dst; int rbase;
    if (m0 < 256)      { dst = g_k; rbase = m0; }
    else if (m0 < 512) { dst = g_q; rbase = m0 - 256; }
    else               { dst = g_v; rbase = m0 - 512; }

#pragma unroll
    for (int i = 0; i < 4; ++i) {
        int row0 = mw + i * 16 + g;
        float bias0 = g_bf[m0 + row0];
        float bias1 = g_bf[m0 + row0 + 8];
#pragma unroll
        for (int j = 0; j < 4; ++j) {
            int col = s0 + nw + j * 8 + tig * 2;
            float* o0 = dst + (size_t)(b * CCH + rbase + row0) * SPA + col;
            float* o1 = o0 + 8 * SPA;
            *(float2*)o0 = make_float2(acc[i][j][0] + bias0, acc[i][j][1] + bias0);
            *(float2*)o1 = make_float2(acc[i][j][2] + bias1, acc[i][j][3] + bias1);
        }
    }
}

// ---------------- K4: k row stats ----------------
__global__ __launch_bounds__(256) void k_kstats() {
    const size_t base = (size_t)blockIdx.x << 14;
    const float4* p = (const float4*)(g_k + base);
    const int tid = threadIdx.x;
    float4 v[16];
    float m = -1e30f;
#pragma unroll
    for (int i = 0; i < 16; ++i) {
        v[i] = p[tid + (i << 8)];
        m = fmaxf(m, fmaxf(fmaxf(v[i].x, v[i].y), fmaxf(v[i].z, v[i].w)));
    }
    __shared__ float sm[256];
    sm[tid] = m; __syncthreads();
    for (int st = 128; st > 0; st >>= 1) {
        if (tid < st) sm[tid] = fmaxf(sm[tid], sm[tid + st]);
        __syncthreads();
    }
    const float rowm = sm[0];
    __syncthreads();
    float l = 0.f;
#pragma unroll
    for (int i = 0; i < 16; ++i)
        l += __expf(v[i].x - rowm) + __expf(v[i].y - rowm)
           + __expf(v[i].z - rowm) + __expf(v[i].w - rowm);
    sm[tid] = l; __syncthreads();
    for (int st = 128; st > 0; st >>= 1) {
        if (tid < st) sm[tid] += sm[tid + st];
        __syncthreads();
    }
    if (tid == 0) {
        g_kmax[blockIdx.x] = rowm;
        g_kinv[blockIdx.x] = 1.f / sm[0];
    }
}

// ---------------- K5: q column stats ----------------
__global__ void k_qstats() {
    int j = blockIdx.x * 256 + threadIdx.x;
    int b = j >> 15;
    int n = (j >> 14) & 1;
    int s = j & 16383;
    const float* col = g_q + ((size_t)(b * CCH + n * HK)) * SPA + s;
    float m = -1e30f, l = 0.f;
    for (int kc = 0; kc < HK; ++kc) {
        float xv = col[(size_t)kc * SPA];
        float nm = fmaxf(m, xv);
        l = l * __expf(m - nm) + __expf(xv - nm);
        m = nm;
    }
    g_qm[j]   = m;
    g_qinv[j] = 1.f / l;
}

// ---------------- K6: context partials softmax(k) @ v^T (fp16, scaled) -------
__global__ __launch_bounds__(256) void k_context() {
    __shared__ uint32_t As[128 * AS_H];
    __shared__ uint32_t Bs[16 * BS_H];
    const int tid = threadIdx.x;
    const int lane = tid & 31, wid = tid >> 5;
    const int g = lane >> 2, tig = lane & 3;
    const int mw = (wid & 1) * 64, nw = (wid >> 1) * 32;

    const int split = blockIdx.x;
    const int bn = blockIdx.y;
    const float* Kb = g_k + ((size_t)bn * HK) * SPA;
    const float* Vb = g_v + ((size_t)bn * HK) * SPA;
    const int sb0 = split * 1024;

    const int row = tid >> 1, sq = (tid & 1) * 16;
    const float km  = g_kmax[bn * HK + row];
    const float kiv = g_kinv[bn * HK + row] * CTX_SCALE;

    float4 pa[4], pb[4];
    float acc[4][4][4] = {};

#pragma unroll
    for (int f = 0; f < 4; ++f) {
        pa[f] = *(const float4*)(Kb + (size_t)row * SPA + sb0 + sq + f * 4);
        pb[f] = *(const float4*)(Vb + (size_t)row * SPA + sb0 + sq + f * 4);
    }
    {
        uint32_t* dA = As + row * AS_H + (sq >> 1);
#pragma unroll
        for (int f = 0; f < 4; ++f) {
            dA[2 * f]     = pk2(__expf(pa[f].x - km) * kiv, __expf(pa[f].y - km) * kiv);
            dA[2 * f + 1] = pk2(__expf(pa[f].z - km) * kiv, __expf(pa[f].w - km) * kiv);
        }
        int rb = sq >> 1;
#pragma unroll
        for (int f = 0; f < 4; ++f) {
            Bs[(rb + 2 * f) * BS_H + row]     = pk2(pb[f].x, pb[f].y);
            Bs[(rb + 2 * f + 1) * BS_H + row] = pk2(pb[f].z, pb[f].w);
        }
    }
    __syncthreads();

    for (int it = 0; it < 32; ++it) {
        const bool more = (it + 1) < 32;
        if (more) {
            const int ks = sb0 + (it + 1) * 32;
#pragma unroll
            for (int f = 0; f < 4; ++f) {
                pa[f] = *(const float4*)(Kb + (size_t)row * SPA + ks + sq + f * 4);
                pb[f] = *(const float4*)(Vb + (size_t)row * SPA + ks + sq + f * 4);
            }
        }
        mma_block16(As, Bs, mw, nw, g, tig, acc);
        __syncthreads();
        if (more) {
            uint32_t* dA = As + row * AS_H + (sq >> 1);
#pragma unroll
            for (int f = 0; f < 4; ++f) {
                dA[2 * f]     = pk2(__expf(pa[f].x - km) * kiv, __expf(pa[f].y - km) * kiv);
                dA[2 * f + 1] = pk2(__expf(pa[f].z - km) * kiv, __expf(pa[f].w - km) * kiv);
            }
            int rb = sq >> 1;
#pragma unroll
            for (int f = 0; f < 4; ++f) {
                Bs[(rb + 2 * f) * BS_H + row]     = pk2(pb[f].x, pb[f].y);
                Bs[(rb + 2 * f + 1) * BS_H + row] = pk2(pb[f].z, pb[f].w);
            }
            __syncthreads();
        }
    }

    float* outp = g_ctx_part + ((size_t)(bn * 16 + split)) * 16384;
#pragma unroll
    for (int i = 0; i < 4; ++i) {
        int row0 = mw + i * 16 + g;
#pragma unroll
        for (int j = 0; j < 4; ++j) {
            int col = nw + j * 8 + tig * 2;
            float* o0 = outp + row0 * 128 + col;
            float* o1 = o0 + 8 * 128;
            *(float2*)o0 = make_float2(acc[i][j][0] * CTX_UNSCALE, acc[i][j][1] * CTX_UNSCALE);
            *(float2*)o1 = make_float2(acc[i][j][2] * CTX_UNSCALE, acc[i][j][3] * CTX_UNSCALE);
        }
    }
}

// ---------------- K7: reduce partials + pooled mean ----------------
__global__ void k_reduce_ctx() {
    const int bn = blockIdx.x;
    const int tid = threadIdx.x;
    float acc = 0.f;
    for (int e = tid; e < 16384; e += 256) {
        float s = 0.f;
#pragma unroll
        for (int p = 0; p < 16; ++p)
            s += g_ctx_part[((size_t)(bn * 16 + p)) * 16384 + e];
        g_context[((size_t)bn << 14) + e] = s;
        acc += s;
    }
    __shared__ float sm[256];
    sm[tid] = acc; __syncthreads();
    for (int st = 128; st > 0; st >>= 1) {
        if (tid < st) sm[tid] += sm[tid + st];
        __syncthreads();
    }
    if (tid == 0) g_pooled[bn] = sm[0] * (1.f / 16384.f);
}

// ---------------- K8: SE gate ----------------
__global__ void k_gate(const float* __restrict__ w_fc1, const float* __restrict__ b_fc1,
                       const float* __restrict__ w_fc2, const float* __restrict__ b_fc2) {
    int b = threadIdx.x;
    if (b >= BATCH) return;
    float p0 = g_pooled[b * 2], p1 = g_pooled[b * 2 + 1];
    float h0 = fmaxf(0.f, p0 * w_fc1[0] + p1 * w_fc1[1] + b_fc1[0]);
    float h1 = fmaxf(0.f, p0 * w_fc1[2] + p1 * w_fc1[3] + b_fc1[1]);
    float z0 = h0 * w_fc2[0] + h1 * w_fc2[1] + b_fc2[0];
    float z1 = h0 * w_fc2[2] + h1 * w_fc2[3] + b_fc2[1];
    g_gate[b * 2]     = 1.f / (1.f + __expf(-z0));
    g_gate[b * 2 + 1] = 1.f / (1.f + __expf(-z1));
}

// ---------------- K9: combine heads ----------------
__global__ void k_combine(const float* __restrict__ w_se) {
    int idx = blockIdx.x * 256 + threadIdx.x;
    int b = idx >> 14;
    int e = idx & 16383;
    float v = w_se[0] * g_gate[b * 2]     * g_context[((size_t)(b * 2))     * 16384 + e]
            + w_se[1] * g_gate[b * 2 + 1] * g_context[((size_t)(b * 2 + 1)) * 16384 + e];
    g_ctx[idx] = v;
}

// ---------------- K10: M_b = w_rep-slices @ ctx_b ----------------
__global__ __launch_bounds__(256) void k_mkM(const float* __restrict__ w_rep) {
    __shared__ float Ws[64][65];
    __shared__ float Cs[64][65];
    const int bid = blockIdx.x;
    const int b = bid >> 4;
    const int rem = bid & 15;
    const int ot = rem >> 2, kt = rem & 3;
    const int n = kt >> 1;
    const int kc0 = (kt & 1) << 6;
    const int o0 = ot << 6;
    const int tid = threadIdx.x;
    const int tx = tid & 15, ty = tid >> 4;
    const float* ctxb = g_ctx + (size_t)b * 16384;
    float acc[4][4] = {};
    const int lrow = tid >> 2;
    const int lc0 = (tid & 3) << 4;
    for (int h = 0; h < 2; ++h) {
        const int vb = n * 128 + h * 64;
#pragma unroll
        for (int f = 0; f < 4; ++f) {
            float4 wv = *(const float4*)(w_rep + (o0 + lrow) * 256 + vb + lc0 + f * 4);
            Ws[lrow][lc0 + f * 4 + 0] = wv.x; Ws[lrow][lc0 + f * 4 + 1] = wv.y;
            Ws[lrow][lc0 + f * 4 + 2] = wv.z; Ws[lrow][lc0 + f * 4 + 3] = wv.w;
            float4 cv = *(const float4*)(ctxb + (kc0 + lrow) * 128 + h * 64 + lc0 + f * 4);
            Cs[lrow][lc0 + f * 4 + 0] = cv.x; Cs[lrow][lc0 + f * 4 + 1] = cv.y;
            Cs[lrow][lc0 + f * 4 + 2] = cv.z; Cs[lrow][lc0 + f * 4 + 3] = cv.w;
        }
        __syncthreads();
        for (int vl = 0; vl < 64; ++vl) {
            float a[4], bb[4];
#pragma unroll
            for (int i = 0; i < 4; ++i) a[i]  = Ws[ty * 4 + i][vl];
#pragma unroll
            for (int j = 0; j < 4; ++j) bb[j] = Cs[tx * 4 + j][vl];
#pragma unroll
            for (int i = 0; i < 4; ++i)
#pragma unroll
                for (int j = 0; j < 4; ++j) acc[i][j] += a[i] * bb[j];
        }
        __syncthreads();
    }
#pragma unroll
    for (int i = 0; i < 4; ++i)
#pragma unroll
        for (int j = 0; j < 4; ++j)
            g_M[(size_t)b * 65536 + (o0 + ty * 4 + i) * 256 + kt * 64 + tx * 4 + j] = acc[i][j];
}

// ---------------- K11: b2 bias fold ----------------
__global__ void k_bias2(const float* __restrict__ w_rep, const float* __restrict__ b_rep,
                        const float* __restrict__ b_se) {
    int o = threadIdx.x;
    float s = 0.f;
    for (int c = 0; c < 256; ++c) s += w_rep[o * 256 + c];
    g_b2[o] = b_rep[o] + b_se[0] * s;
}

// ---------------- K12: fused final GEMM M_b @ softmax_q + b2 (fp16) ----------
__global__ __launch_bounds__(256) void k_final_fused(float* __restrict__ out) {
    __shared__ uint32_t As[128 * AS_H];
    __shared__ uint32_t Bs[16 * BS_H];
    const int tid = threadIdx.x;
    const int lane = tid & 31, wid = tid >> 5;
    const int g = lane >> 2, tig = lane & 3;
    const int mw = (wid & 1) * 64, nw = (wid >> 1) * 32;

    const int m0 = blockIdx.x << 7;
    const int by = blockIdx.y;
    const int b = by >> 7, s0 = (by & 127) << 7;
    const float* Am = g_M + (size_t)b * 65536;
    const float* Bq = g_q + (size_t)b * CCH * SPA;
    const float* qm = g_qm   + ((size_t)(b * 2) << 14);
    const float* qi = g_qinv + ((size_t)(b * 2) << 14);

    const int ar = tid >> 1, ak = (tid & 1) * 16;
    const int bkp = tid >> 4, bs = (tid & 15) * 8;

    float4 pa[4], pb[4];
    float acc[4][4][4] = {};

#pragma unroll
    for (int f = 0; f < 4; ++f)
        pa[f] = *(const float4*)(Am + (m0 + ar) * 256 + ak + f * 4);
    {
        const float* r0 = Bq + (size_t)(2 * bkp) * SPA + s0 + bs;
        pb[0] = *(const float4*)r0;  pb[1] = *(const float4*)(r0 + 4);
        pb[2] = *(const float4*)(r0 + SPA); pb[3] = *(const float4*)(r0 + SPA + 4);
    }
    {
        uint32_t* dA = As + ar * AS_H + (ak >> 1);
        dA[0] = pk2(pa[0].x, pa[0].y); dA[1] = pk2(pa[0].z, pa[0].w);
        dA[2] = pk2(pa[1].x, pa[1].y); dA[3] = pk2(pa[1].z, pa[1].w);
        dA[4] = pk2(pa[2].x, pa[2].y); dA[5] = pk2(pa[2].z, pa[2].w);
        dA[6] = pk2(pa[3].x, pa[3].y); dA[7] = pk2(pa[3].z, pa[3].w);
        float4 mv0 = *(const float4*)(qm + s0 + bs);
        float4 mv1 = *(const float4*)(qm + s0 + bs + 4);
        float4 iv0 = *(const float4*)(qi + s0 + bs);
        float4 iv1 = *(const float4*)(qi + s0 + bs + 4);
        uint32_t* dB = Bs + bkp * BS_H + bs;
        dB[0] = pk2(__expf(pb[0].x - mv0.x) * iv0.x, __expf(pb[2].x - mv0.x) * iv0.x);
        dB[1] = pk2(__expf(pb[0].y - mv0.y) * iv0.y, __expf(pb[2].y - mv0.y) * iv0.y);
        dB[2] = pk2(__expf(pb[0].z - mv0.z) * iv0.z, __expf(pb[2].z - mv0.z) * iv0.z);
        dB[3] = pk2(__expf(pb[0].w - mv0.w) * iv0.w, __expf(pb[2].w - mv0.w) * iv0.w);
        dB[4] = pk2(__expf(pb[1].x - mv1.x) * iv1.x, __expf(pb[3].x - mv1.x) * iv1.x);
        dB[5] = pk2(__expf(pb[1].y - mv1.y) * iv1.y, __expf(pb[3].y - mv1.y) * iv1.y);
        dB[6] = pk2(__expf(pb[1].z - mv1.z) * iv1.z, __expf(pb[3].z - mv1.z) * iv1.z);
        dB[7] = pk2(__expf(pb[1].w - mv1.w) * iv1.w, __expf(pb[3].w - mv1.w) * iv1.w);
    }
    __syncthreads();

    for (int it = 0; it < 8; ++it) {
        const bool more = (it + 1) < 8;
        const int ksn = (it + 1) * 32;
        if (more) {
#pragma unroll
            for (int f = 0; f < 4; ++f)
                pa[f] = *(const float4*)(Am + (m0 + ar) * 256 + ksn + ak + f * 4);
            const float* r0 = Bq + (size_t)(ksn + 2 * bkp) * SPA + s0 + bs;
            pb[0] = *(const float4*)r0;  pb[1] = *(const float4*)(r0 + 4);
            pb[2] = *(const float4*)(r0 + SPA); pb[3] = *(const float4*)(r0 + SPA + 4);
        }
        mma_block16(As, Bs, mw, nw, g, tig, acc);
        __syncthreads();
        if (more) {
            const int nbh = (ksn >> 7) << 14;    // head select for staged rows
            uint32_t* dA = As + ar * AS_H + (ak >> 1);
            dA[0] = pk2(pa[0].x, pa[0].y); dA[1] = pk2(pa[0].z, pa[0].w);
            dA[2] = pk2(pa[1].x, pa[1].y); dA[3] = pk2(pa[1].z, pa[1].w);
            dA[4] = pk2(pa[2].x, pa[2].y); dA[5] = pk2(pa[2].z, pa[2].w);
            dA[6] = pk2(pa[3].x, pa[3].y); dA[7] = pk2(pa[3].z, pa[3].w);
            float4 mv0 = *(const float4*)(qm + nbh + s0 + bs);
            float4 mv1 = *(const float4*)(qm + nbh + s0 + bs + 4);
            float4 iv0 = *(const float4*)(qi + nbh + s0 + bs);
            float4 iv1 = *(const float4*)(qi + nbh + s0 + bs + 4);
            uint32_t* dB = Bs + bkp * BS_H + bs;
            dB[0] = pk2(__expf(pb[0].x - mv0.x) * iv0.x, __expf(pb[2].x - mv0.x) * iv0.x);
            dB[1] = pk2(__expf(pb[0].y - mv0.y) * iv0.y, __expf(pb[2].y - mv0.y) * iv0.y);
            dB[2] = pk2(__expf(pb[0].z - mv0.z) * iv0.z, __expf(pb[2].z - mv0.z) * iv0.z);
            dB[3] = pk2(__expf(pb[0].w - mv0.w) * iv0.w, __expf(pb[2].w - mv0.w) * iv0.w);
            dB[4] = pk2(__expf(pb[1].x - mv1.x) * iv1.x, __expf(pb[3].x - mv1.x) * iv1.x);
            dB[5] = pk2(__expf(pb[1].y - mv1.y) * iv1.y, __expf(pb[3].y - mv1.y) * iv1.y);
            dB[6] = pk2(__expf(pb[1].z - mv1.z) * iv1.z, __expf(pb[3].z - mv1.z) * iv1.z);
            dB[7] = pk2(__expf(pb[1].w - mv1.w) * iv1.w, __expf(pb[3].w - mv1.w) * iv1.w);
            __syncthreads();
        }
    }

#pragma unroll
    for (int i = 0; i < 4; ++i) {
        int row0 = m0 + mw + i * 16 + g;
        float bias0 = g_b2[row0];
        float bias1 = g_b2[row0 + 8];
#pragma unroll
        for (int j = 0; j < 4; ++j) {
            int col = s0 + nw + j * 8 + tig * 2;
            float* o0 = out + (size_t)(b * CCH + row0) * SPA + col;
            float* o1 = o0 + (size_t)8 * SPA;
            *(float2*)o0 = make_float2(acc[i][j][0] + bias0, acc[i][j][1] + bias0);
            *(float2*)o1 = make_float2(acc[i][j][2] + bias1, acc[i][j][3] + bias1);
        }
    }
}

// ---------------- launch ----------------
extern "C" void kernel_launch(void* const* d_in, const int* in_sizes, int n_in,
                              void* d_out, int out_size) {
    const float* x     = (const float*)d_in[0];
    const float* gamma = (const float*)d_in[1];
    const float* beta  = (const float*)d_in[2];
    const float* wk    = (const float*)d_in[3];
    const float* bk    = (const float*)d_in[4];
    const float* wq    = (const float*)d_in[5];
    const float* bq    = (const float*)d_in[6];
    const float* wv    = (const float*)d_in[7];
    const float* bv    = (const float*)d_in[8];
    const float* w_fc1 = (const float*)d_in[9];
    const float* b_fc1 = (const float*)d_in[10];
    const float* w_fc2 = (const float*)d_in[11];
    const float* b_fc2 = (const float*)d_in[12];
    const float* w_se  = (const float*)d_in[13];
    const float* b_se  = (const float*)d_in[14];
    const float* w_rep = (const float*)d_in[15];
    const float* b_rep = (const float*)d_in[16];
    float* out = (float*)d_out;

    k_bnstats<<<256, 256>>>(x);
    k_fuseW<<<3, 256>>>(wk, bk, wq, bq, wv, bv, gamma, beta);
    k_gemm_kqv<<<dim3(6, 1024), 256>>>(x);
    k_kstats<<<2048, 256>>>();
    k_qstats<<<1024, 256>>>();
    k_context<<<dim3(16, 16), 256>>>();
    k_reduce_ctx<<<16, 256>>>();
    k_gate<<<1, 32>>>(w_fc1, b_fc1, w_fc2, b_fc2);
    k_combine<<<512, 256>>>(w_se);
    k_mkM<<<128, 256>>>(w_rep);
    k_bias2<<<1, 256>>>(w_rep, b_rep, b_se);
    k_final_fused<<<dim3(2, 1024), 256>>>(out);
}

// round 7
// speedup vs baseline: 2.0026x; 1.0190x over previous
#include <cuda_runtime.h>
#include <cuda_fp16.h>
#include <cstdint>

#define BATCH 8
#define CCH   256
#define SPA   16384
#define HEADS 2
#define HK    128

// ---------------- scratch ----------------
__device__ float  g_mean[CCH];
__device__ float  g_rstd[CCH];
__device__ float  g_wf[768 * 256];
__device__ float  g_bf[768];
__device__ __half g_k[BATCH * CCH * SPA];   // fp16 storage (67 MB each)
__device__ __half g_q[BATCH * CCH * SPA];
__device__ __half g_v[BATCH * CCH * SPA];
__device__ float  g_ctx_part[16 * 16 * 128 * 128];
__device__ float  g_context[16 * 128 * 128];
__device__ float  g_ctx[BATCH * 128 * 128];
__device__ float  g_pooled[16];
__device__ float  g_gate[16];
__device__ float  g_kmax[2048];
__device__ float  g_kinv[2048];
__device__ float  g_qm[BATCH * 2 * SPA];
__device__ float  g_qinv[BATCH * 2 * SPA];
__device__ float  g_M[BATCH * 256 * 256];
__device__ float  g_b2[256];

#define CTX_SCALE      16384.0f
#define CTX_UNSCALE    (1.0f / 16384.0f)

// ---------------- fp16 mma helpers ----------------
__device__ __forceinline__ uint32_t pk2(float lo, float hi) {
    uint32_t r;
    asm("cvt.rn.f16x2.f32 %0, %1, %2;" : "=r"(r) : "f"(hi), "f"(lo));
    return r;
}
__device__ __forceinline__ float2 h2f(uint32_t w) {
    __half2 h = *reinterpret_cast<__half2*>(&w);
    return __half22float2(h);
}

__device__ __forceinline__ void mma_f16(float c[4], const uint32_t a[4], const uint32_t b[2]) {
    asm volatile(
        "mma.sync.aligned.m16n8k16.row.col.f32.f16.f16.f32 "
        "{%0,%1,%2,%3}, {%4,%5,%6,%7}, {%8,%9}, {%0,%1,%2,%3};"
        : "+f"(c[0]), "+f"(c[1]), "+f"(c[2]), "+f"(c[3])
        : "r"(a[0]), "r"(a[1]), "r"(a[2]), "r"(a[3]), "r"(b[0]), "r"(b[1]));
}

#define AS_H 20
#define BS_H 136

__device__ __forceinline__ void mma_block16(const uint32_t* __restrict__ As,
                                            const uint32_t* __restrict__ Bs,
                                            int mw, int nw, int g, int tig,
                                            float (&acc)[4][4][4]) {
#pragma unroll
    for (int ks2 = 0; ks2 < 16; ks2 += 8) {
        uint32_t a[4][4], b[4][2];
#pragma unroll
        for (int i = 0; i < 4; ++i) {
            const uint32_t* A0 = As + (mw + i * 16 + g) * AS_H + ks2;
            const uint32_t* A1 = A0 + 8 * AS_H;
            a[i][0] = A0[tig];     a[i][1] = A1[tig];
            a[i][2] = A0[tig + 4]; a[i][3] = A1[tig + 4];
        }
#pragma unroll
        for (int j = 0; j < 4; ++j) {
            int cb = nw + j * 8 + g;
            b[j][0] = Bs[(ks2 + tig) * BS_H + cb];
            b[j][1] = Bs[(ks2 + tig + 4) * BS_H + cb];
        }
#pragma unroll
        for (int i = 0; i < 4; ++i)
#pragma unroll
            for (int j = 0; j < 4; ++j)
                mma_f16(acc[i][j], a[i], b[j]);
    }
}

// ---------------- K1: BatchNorm statistics ----------------
__global__ void k_bnstats(const float* __restrict__ x) {
    const int c = blockIdx.x;
    const int tid = threadIdx.x;
    float s = 0.f, s2 = 0.f;
    for (int b = 0; b < BATCH; ++b) {
        const float4* p = (const float4*)(x + ((size_t)(b * CCH + c) << 14));
        for (int i = tid; i < SPA / 4; i += 256) {
            float4 v = p[i];
            s  += v.x + v.y + v.z + v.w;
            s2 += v.x * v.x + v.y * v.y + v.z * v.z + v.w * v.w;
        }
    }
    __shared__ float sa[256], sb[256];
    sa[tid] = s; sb[tid] = s2;
    __syncthreads();
    for (int st = 128; st > 0; st >>= 1) {
        if (tid < st) { sa[tid] += sa[tid + st]; sb[tid] += sb[tid + st]; }
        __syncthreads();
    }
    if (tid == 0) {
        const float inv_n = 1.f / (float)(BATCH * SPA);
        float mean = sa[0] * inv_n;
        float var  = sb[0] * inv_n - mean * mean;
        g_mean[c] = mean;
        g_rstd[c] = rsqrtf(var + 1e-5f);
    }
}

// ---------------- K2: fold BN into kqv weights ----------------
__global__ void k_fuseW(const float* __restrict__ wk, const float* __restrict__ bk,
                        const float* __restrict__ wq, const float* __restrict__ bq,
                        const float* __restrict__ wv, const float* __restrict__ bv,
                        const float* __restrict__ gamma, const float* __restrict__ beta) {
    int o = blockIdx.x * blockDim.x + threadIdx.x;
    if (o >= 768) return;
    const float* W; const float* bias; int r;
    if (o < 256)      { W = wk; bias = bk; r = o; }
    else if (o < 512) { W = wq; bias = bq; r = o - 256; }
    else              { W = wv; bias = bv; r = o - 512; }
    float bacc = bias[r];
    for (int c = 0; c < 256; ++c) {
        float a = g_rstd[c] * gamma[c];
        float d = beta[c] - g_mean[c] * a;
        float w = W[r * 256 + c];
        g_wf[o * 256 + c] = w * a;
        bacc += w * d;
    }
    g_bf[o] = bacc;
}

// ---------------- K3: fused kqv GEMM (fp16, double-buffered) ----------------
__global__ __launch_bounds__(256) void k_gemm_kqv(const float* __restrict__ x) {
    __shared__ uint32_t As[2][128 * AS_H];
    __shared__ uint32_t Bs[2][16 * BS_H];
    const int tid = threadIdx.x;
    const int lane = tid & 31, wid = tid >> 5;
    const int g = lane >> 2, tig = lane & 3;
    const int mw = (wid & 1) * 64, nw = (wid >> 1) * 32;

    const int m0 = blockIdx.x << 7;
    const int by = blockIdx.y;
    const int b = by >> 7, s0 = (by & 127) << 7;
    const float* Bbase = x + ((size_t)b * CCH) * SPA;

    const int ar = tid >> 1, ak = (tid & 1) * 16;
    const int bkp = tid >> 4, bs = (tid & 15) * 8;

    float4 pa[4], pb[4];
    float acc[4][4][4] = {};

#define KQV_LOAD(ks) do { \
    _Pragma("unroll") \
    for (int f = 0; f < 4; ++f) \
        pa[f] = *(const float4*)(g_wf + (m0 + ar) * 256 + (ks) + ak + f * 4); \
    const float* r0_ = Bbase + (size_t)((ks) + 2 * bkp) * SPA + s0 + bs; \
    pb[0] = *(const float4*)r0_;  pb[1] = *(const float4*)(r0_ + 4); \
    pb[2] = *(const float4*)(r0_ + SPA); pb[3] = *(const float4*)(r0_ + SPA + 4); \
} while (0)

#define KQV_STAGE(buf) do { \
    uint32_t* dA = As[buf] + ar * AS_H + (ak >> 1); \
    dA[0] = pk2(pa[0].x, pa[0].y); dA[1] = pk2(pa[0].z, pa[0].w); \
    dA[2] = pk2(pa[1].x, pa[1].y); dA[3] = pk2(pa[1].z, pa[1].w); \
    dA[4] = pk2(pa[2].x, pa[2].y); dA[5] = pk2(pa[2].z, pa[2].w); \
    dA[6] = pk2(pa[3].x, pa[3].y); dA[7] = pk2(pa[3].z, pa[3].w); \
    uint32_t* dB = Bs[buf] + bkp * BS_H + bs; \
    dB[0] = pk2(pb[0].x, pb[2].x); dB[1] = pk2(pb[0].y, pb[2].y); \
    dB[2] = pk2(pb[0].z, pb[2].z); dB[3] = pk2(pb[0].w, pb[2].w); \
    dB[4] = pk2(pb[1].x, pb[3].x); dB[5] = pk2(pb[1].y, pb[3].y); \
    dB[6] = pk2(pb[1].z, pb[3].z); dB[7] = pk2(pb[1].w, pb[3].w); \
} while (0)

    KQV_LOAD(0);
    KQV_STAGE(0);
    KQV_LOAD(32);
    __syncthreads();

    for (int it = 0; it < 8; ++it) {
        const int cur = it & 1;
        if (it + 1 < 8) KQV_STAGE(cur ^ 1);
        if (it + 2 < 8) KQV_LOAD((it + 2) * 32);
        mma_block16(As[cur], Bs[cur], mw, nw, g, tig, acc);
        __syncthreads();
    }

    __half* dst; int rbase;
    if (m0 < 256)      { dst = g_k; rbase = m0; }
    else if (m0 < 512) { dst = g_q; rbase = m0 - 256; }
    else               { dst = g_v; rbase = m0 - 512; }

#pragma unroll
    for (int i = 0; i < 4; ++i) {
        int row0 = mw + i * 16 + g;
        float bias0 = g_bf[m0 + row0];
        float bias1 = g_bf[m0 + row0 + 8];
#pragma unroll
        for (int j = 0; j < 4; ++j) {
            int col = s0 + nw + j * 8 + tig * 2;
            __half* o0 = dst + (size_t)(b * CCH + rbase + row0) * SPA + col;
            *(uint32_t*)o0 = pk2(acc[i][j][0] + bias0, acc[i][j][1] + bias0);
            *(uint32_t*)(o0 + (size_t)8 * SPA) = pk2(acc[i][j][2] + bias1, acc[i][j][3] + bias1);
        }
    }
}

// ---------------- K4: k row stats (fp16 reads) ----------------
__global__ __launch_bounds__(256) void k_kstats() {
    const uint4* p = (const uint4*)(g_k + ((size_t)blockIdx.x << 14));
    const int tid = threadIdx.x;
    uint4 v[8];
    float m = -1e30f;
#pragma unroll
    for (int i = 0; i < 8; ++i) {
        v[i] = p[tid + (i << 8)];
        const uint32_t* w = (const uint32_t*)&v[i];
#pragma unroll
        for (int q = 0; q < 4; ++q) {
            float2 f = h2f(w[q]);
            m = fmaxf(m, fmaxf(f.x, f.y));
        }
    }
    __shared__ float sm[256];
    sm[tid] = m; __syncthreads();
    for (int st = 128; st > 0; st >>= 1) {
        if (tid < st) sm[tid] = fmaxf(sm[tid], sm[tid + st]);
        __syncthreads();
    }
    const float rowm = sm[0];
    __syncthreads();
    float l = 0.f;
#pragma unroll
    for (int i = 0; i < 8; ++i) {
        const uint32_t* w = (const uint32_t*)&v[i];
#pragma unroll
        for (int q = 0; q < 4; ++q) {
            float2 f = h2f(w[q]);
            l += __expf(f.x - rowm) + __expf(f.y - rowm);
        }
    }
    sm[tid] = l; __syncthreads();
    for (int st = 128; st > 0; st >>= 1) {
        if (tid < st) sm[tid] += sm[tid + st];
        __syncthreads();
    }
    if (tid == 0) {
        g_kmax[blockIdx.x] = rowm;
        g_kinv[blockIdx.x] = 1.f / sm[0];
    }
}

// ---------------- K5: q column stats (fp16 reads) ----------------
__global__ void k_qstats() {
    int j = blockIdx.x * 256 + threadIdx.x;
    int b = j >> 15;
    int n = (j >> 14) & 1;
    int s = j & 16383;
    const __half* col = g_q + ((size_t)(b * CCH + n * HK)) * SPA + s;
    float m = -1e30f, l = 0.f;
    for (int kc = 0; kc < HK; ++kc) {
        float xv = __half2float(col[(size_t)kc * SPA]);
        float nm = fmaxf(m, xv);
        l = l * __expf(m - nm) + __expf(xv - nm);
        m = nm;
    }
    g_qm[j]   = m;
    g_qinv[j] = 1.f / l;
}

// ---------------- K6: context softmax(k) @ v^T (fp16, double-buffered) -------
__global__ __launch_bounds__(256) void k_context() {
    __shared__ uint32_t As[2][128 * AS_H];
    __shared__ uint32_t Bs[2][16 * BS_H];
    const int tid = threadIdx.x;
    const int lane = tid & 31, wid = tid >> 5;
    const int g = lane >> 2, tig = lane & 3;
    const int mw = (wid & 1) * 64, nw = (wid >> 1) * 32;

    const int split = blockIdx.x;
    const int bn = blockIdx.y;
    const __half* Kb = g_k + ((size_t)bn * HK) * SPA;
    const __half* Vb = g_v + ((size_t)bn * HK) * SPA;
    const int sb0 = split * 1024;

    const int row = tid >> 1, sq = (tid & 1) * 16;
    const float km  = g_kmax[bn * HK + row];
    const float kiv = g_kinv[bn * HK + row] * CTX_SCALE;

    uint4 ra0, ra1, rb0, rb1;
    float acc[4][4][4] = {};

#define CTX_LOAD(ks) do { \
    const uint4* ksrc = (const uint4*)(Kb + (size_t)row * SPA + (ks) + sq); \
    ra0 = ksrc[0]; ra1 = ksrc[1]; \
    const uint4* vsrc = (const uint4*)(Vb + (size_t)row * SPA + (ks) + sq); \
    rb0 = vsrc[0]; rb1 = vsrc[1]; \
} while (0)

#define CTX_STAGE(buf) do { \
    uint32_t* dA = As[buf] + row * AS_H + (sq >> 1); \
    const uint32_t* wa = (const uint32_t*)&ra0; \
    _Pragma("unroll") \
    for (int q = 0; q < 4; ++q) { \
        float2 f = h2f(wa[q]); \
        dA[q] = pk2(__expf(f.x - km) * kiv, __expf(f.y - km) * kiv); \
    } \
    const uint32_t* wa1 = (const uint32_t*)&ra1; \
    _Pragma("unroll") \
    for (int q = 0; q < 4; ++q) { \
        float2 f = h2f(wa1[q]); \
        dA[4 + q] = pk2(__expf(f.x - km) * kiv, __expf(f.y - km) * kiv); \
    } \
    const int rbo = sq >> 1; \
    uint32_t* BB = Bs[buf]; \
    BB[(rbo + 0) * BS_H + row] = rb0.x; BB[(rbo + 1) * BS_H + row] = rb0.y; \
    BB[(rbo + 2) * BS_H + row] = rb0.z; BB[(rbo + 3) * BS_H + row] = rb0.w; \
    BB[(rbo + 4) * BS_H + row] = rb1.x; BB[(rbo + 5) * BS_H + row] = rb1.y; \
    BB[(rbo + 6) * BS_H + row] = rb1.z; BB[(rbo + 7) * BS_H + row] = rb1.w; \
} while (0)

    CTX_LOAD(sb0);
    CTX_STAGE(0);
    CTX_LOAD(sb0 + 32);
    __syncthreads();

    for (int it = 0; it < 32; ++it) {
        const int cur = it & 1;
        if (it + 1 < 32) CTX_STAGE(cur ^ 1);
        if (it + 2 < 32) CTX_LOAD(sb0 + (it + 2) * 32);
        mma_block16(As[cur], Bs[cur], mw, nw, g, tig, acc);
        __syncthreads();
    }

    float* outp = g_ctx_part + ((size_t)(bn * 16 + split)) * 16384;
#pragma unroll
    for (int i = 0; i < 4; ++i) {
        int row0 = mw + i * 16 + g;
#pragma unroll
        for (int j = 0; j < 4; ++j) {
            int col = nw + j * 8 + tig * 2;
            float* o0 = outp + row0 * 128 + col;
            float* o1 = o0 + 8 * 128;
            *(float2*)o0 = make_float2(acc[i][j][0] * CTX_UNSCALE, acc[i][j][1] * CTX_UNSCALE);
            *(float2*)o1 = make_float2(acc[i][j][2] * CTX_UNSCALE, acc[i][j][3] * CTX_UNSCALE);
        }
    }
}

// ---------------- K7: reduce partials + pooled mean ----------------
__global__ void k_reduce_ctx() {
    const int bn = blockIdx.x;
    const int tid = threadIdx.x;
    float acc = 0.f;
    for (int e = tid; e < 16384; e += 256) {
        float s = 0.f;
#pragma unroll
        for (int p = 0; p < 16; ++p)
            s += g_ctx_part[((size_t)(bn * 16 + p)) * 16384 + e];
        g_context[((size_t)bn << 14) + e] = s;
        acc += s;
    }
    __shared__ float sm[256];
    sm[tid] = acc; __syncthreads();
    for (int st = 128; st > 0; st >>= 1) {
        if (tid < st) sm[tid] += sm[tid + st];
        __syncthreads();
    }
    if (tid == 0) g_pooled[bn] = sm[0] * (1.f / 16384.f);
}

// ---------------- K8: SE gate ----------------
__global__ void k_gate(const float* __restrict__ w_fc1, const float* __restrict__ b_fc1,
                       const float* __restrict__ w_fc2, const float* __restrict__ b_fc2) {
    int b = threadIdx.x;
    if (b >= BATCH) return;
    float p0 = g_pooled[b * 2], p1 = g_pooled[b * 2 + 1];
    float h0 = fmaxf(0.f, p0 * w_fc1[0] + p1 * w_fc1[1] + b_fc1[0]);
    float h1 = fmaxf(0.f, p0 * w_fc1[2] + p1 * w_fc1[3] + b_fc1[1]);
    float z0 = h0 * w_fc2[0] + h1 * w_fc2[1] + b_fc2[0];
    float z1 = h0 * w_fc2[2] + h1 * w_fc2[3] + b_fc2[1];
    g_gate[b * 2]     = 1.f / (1.f + __expf(-z0));
    g_gate[b * 2 + 1] = 1.f / (1.f + __expf(-z1));
}

// ---------------- K9: combine heads ----------------
__global__ void k_combine(const float* __restrict__ w_se) {
    int idx = blockIdx.x * 256 + threadIdx.x;
    int b = idx >> 14;
    int e = idx & 16383;
    float v = w_se[0] * g_gate[b * 2]     * g_context[((size_t)(b * 2))     * 16384 + e]
            + w_se[1] * g_gate[b * 2 + 1] * g_context[((size_t)(b * 2 + 1)) * 16384 + e];
    g_ctx[idx] = v;
}

// ---------------- K10: M_b = w_rep-slices @ ctx_b ----------------
__global__ __launch_bounds__(256) void k_mkM(const float* __restrict__ w_rep) {
    __shared__ float Ws[64][65];
    __shared__ float Cs[64][65];
    const int bid = blockIdx.x;
    const int b = bid >> 4;
    const int rem = bid & 15;
    const int ot = rem >> 2, kt = rem & 3;
    const int n = kt >> 1;
    const int kc0 = (kt & 1) << 6;
    const int o0 = ot << 6;
    const int tid = threadIdx.x;
    const int tx = tid & 15, ty = tid >> 4;
    const float* ctxb = g_ctx + (size_t)b * 16384;
    float acc[4][4] = {};
    const int lrow = tid >> 2;
    const int lc0 = (tid & 3) << 4;
    for (int h = 0; h < 2; ++h) {
        const int vb = n * 128 + h * 64;
#pragma unroll
        for (int f = 0; f < 4; ++f) {
            float4 wv = *(const float4*)(w_rep + (o0 + lrow) * 256 + vb + lc0 + f * 4);
            Ws[lrow][lc0 + f * 4 + 0] = wv.x; Ws[lrow][lc0 + f * 4 + 1] = wv.y;
            Ws[lrow][lc0 + f * 4 + 2] = wv.z; Ws[lrow][lc0 + f * 4 + 3] = wv.w;
            float4 cv = *(const float4*)(ctxb + (kc0 + lrow) * 128 + h * 64 + lc0 + f * 4);
            Cs[lrow][lc0 + f * 4 + 0] = cv.x; Cs[lrow][lc0 + f * 4 + 1] = cv.y;
            Cs[lrow][lc0 + f * 4 + 2] = cv.z; Cs[lrow][lc0 + f * 4 + 3] = cv.w;
        }
        __syncthreads();
        for (int vl = 0; vl < 64; ++vl) {
            float a[4], bb[4];
#pragma unroll
            for (int i = 0; i < 4; ++i) a[i]  = Ws[ty * 4 + i][vl];
#pragma unroll
            for (int j = 0; j < 4; ++j) bb[j] = Cs[tx * 4 + j][vl];
#pragma unroll
            for (int i = 0; i < 4; ++i)
#pragma unroll
                for (int j = 0; j < 4; ++j) acc[i][j] += a[i] * bb[j];
        }
        __syncthreads();
    }
#pragma unroll
    for (int i = 0; i < 4; ++i)
#pragma unroll
        for (int j = 0; j < 4; ++j)
            g_M[(size_t)b * 65536 + (o0 + ty * 4 + i) * 256 + kt * 64 + tx * 4 + j] = acc[i][j];
}

// ---------------- K11: b2 bias fold ----------------
__global__ void k_bias2(const float* __restrict__ w_rep, const float* __restrict__ b_rep,
                        const float* __restrict__ b_se) {
    int o = threadIdx.x;
    float s = 0.f;
    for (int c = 0; c < 256; ++c) s += w_rep[o * 256 + c];
    g_b2[o] = b_rep[o] + b_se[0] * s;
}

// ---------------- K12: fused final GEMM (fp16, double-buffered) ----------
__global__ __launch_bounds__(256) void k_final_fused(float* __restrict__ out) {
    __shared__ uint32_t As[2][128 * AS_H];
    __shared__ uint32_t Bs[2][16 * BS_H];
    const int tid = threadIdx.x;
    const int lane = tid & 31, wid = tid >> 5;
    const int g = lane >> 2, tig = lane & 3;
    const int mw = (wid & 1) * 64, nw = (wid >> 1) * 32;

    const int m0 = blockIdx.x << 7;
    const int by = blockIdx.y;
    const int b = by >> 7, s0 = (by & 127) << 7;
    const float* Am = g_M + (size_t)b * 65536;
    const __half* Bq = g_q + (size_t)b * CCH * SPA;
    const float* qm = g_qm   + ((size_t)(b * 2) << 14);
    const float* qi = g_qinv + ((size_t)(b * 2) << 14);

    const int ar = tid >> 1, ak = (tid & 1) * 16;
    const int bkp = tid >> 4, bs = (tid & 15) * 8;

    float4 pa[4], mv0, mv1, iv0, iv1;
    uint4 rb0, rb1;
    float acc[4][4][4] = {};

#define FIN_LOAD(ks) do { \
    _Pragma("unroll") \
    for (int f = 0; f < 4; ++f) \
        pa[f] = *(const float4*)(Am + (m0 + ar) * 256 + (ks) + ak + f * 4); \
    const __half* q0_ = Bq + (size_t)((ks) + 2 * bkp) * SPA + s0 + bs; \
    rb0 = *(const uint4*)q0_; \
    rb1 = *(const uint4*)(q0_ + SPA); \
    const int nbh_ = ((ks) >> 7) << 14; \
    mv0 = *(const float4*)(qm + nbh_ + s0 + bs); \
    mv1 = *(const float4*)(qm + nbh_ + s0 + bs + 4); \
    iv0 = *(const float4*)(qi + nbh_ + s0 + bs); \
    iv1 = *(const float4*)(qi + nbh_ + s0 + bs + 4); \
} while (0)

#define FIN_STAGE(buf) do { \
    uint32_t* dA = As[buf] + ar * AS_H + (ak >> 1); \
    dA[0] = pk2(pa[0].x, pa[0].y); dA[1] = pk2(pa[0].z, pa[0].w); \
    dA[2] = pk2(pa[1].x, pa[1].y); dA[3] = pk2(pa[1].z, pa[1].w); \
    dA[4] = pk2(pa[2].x, pa[2].y); dA[5] = pk2(pa[2].z, pa[2].w); \
    dA[6] = pk2(pa[3].x, pa[3].y); dA[7] = pk2(pa[3].z, pa[3].w); \
    const uint32_t* w0 = (const uint32_t*)&rb0; \
    const uint32_t* w1 = (const uint32_t*)&rb1; \
    float e0[8], e1[8]; \
    { float2 f; \
      f = h2f(w0[0]); e0[0] = __expf(f.x - mv0.x) * iv0.x; e0[1] = __expf(f.y - mv0.y) * iv0.y; \
      f = h2f(w0[1]); e0[2] = __expf(f.x - mv0.z) * iv0.z; e0[3] = __expf(f.y - mv0.w) * iv0.w; \
      f = h2f(w0[2]); e0[4] = __expf(f.x - mv1.x) * iv1.x; e0[5] = __expf(f.y - mv1.y) * iv1.y; \
      f = h2f(w0[3]); e0[6] = __expf(f.x - mv1.z) * iv1.z; e0[7] = __expf(f.y - mv1.w) * iv1.w; \
      f = h2f(w1[0]); e1[0] = __expf(f.x - mv0.x) * iv0.x; e1[1] = __expf(f.y - mv0.y) * iv0.y; \
      f = h2f(w1[1]); e1[2] = __expf(f.x - mv0.z) * iv0.z; e1[3] = __expf(f.y - mv0.w) * iv0.w; \
      f = h2f(w1[2]); e1[4] = __expf(f.x - mv1.x) * iv1.x; e1[5] = __expf(f.y - mv1.y) * iv1.y; \
      f = h2f(w1[3]); e1[6] = __expf(f.x - mv1.z) * iv1.z; e1[7] = __expf(f.y - mv1.w) * iv1.w; } \
    uint32_t* dB = Bs[buf] + bkp * BS_H + bs; \
    _Pragma("unroll") \
    for (int q = 0; q < 8; ++q) dB[q] = pk2(e0[q], e1[q]); \
} while (0)

    FIN_LOAD(0);
    FIN_STAGE(0);
    FIN_LOAD(32);
    __syncthreads();

    for (int it = 0; it < 8; ++it) {
        const int cur = it & 1;
        if (it + 1 < 8) FIN_STAGE(cur ^ 1);
        if (it + 2 < 8) FIN_LOAD((it + 2) * 32);
        mma_block16(As[cur], Bs[cur], mw, nw, g, tig, acc);
        __syncthreads();
    }

#pragma unroll
    for (int i = 0; i < 4; ++i) {
        int row0 = m0 + mw + i * 16 + g;
        float bias0 = g_b2[row0];
        float bias1 = g_b2[row0 + 8];
#pragma unroll
        for (int j = 0; j < 4; ++j) {
            int col = s0 + nw + j * 8 + tig * 2;
            float* o0 = out + (size_t)(b * CCH + row0) * SPA + col;
            float* o1 = o0 + (size_t)8 * SPA;
            *(float2*)o0 = make_float2(acc[i][j][0] + bias0, acc[i][j][1] + bias0);
            *(float2*)o1 = make_float2(acc[i][j][2] + bias1, acc[i][j][3] + bias1);
        }
    }
}

// ---------------- launch ----------------
extern "C" void kernel_launch(void* const* d_in, const int* in_sizes, int n_in,
                              void* d_out, int out_size) {
    const float* x     = (const float*)d_in[0];
    const float* gamma = (const float*)d_in[1];
    const float* beta  = (const float*)d_in[2];
    const float* wk    = (const float*)d_in[3];
    const float* bk    = (const float*)d_in[4];
    const float* wq    = (const float*)d_in[5];
    const float* bq    = (const float*)d_in[6];
    const float* wv    = (const float*)d_in[7];
    const float* bv    = (const float*)d_in[8];
    const float* w_fc1 = (const float*)d_in[9];
    const float* b_fc1 = (const float*)d_in[10];
    const float* w_fc2 = (const float*)d_in[11];
    const float* b_fc2 = (const float*)d_in[12];
    const float* w_se  = (const float*)d_in[13];
    const float* b_se  = (const float*)d_in[14];
    const float* w_rep = (const float*)d_in[15];
    const float* b_rep = (const float*)d_in[16];
    float* out = (float*)d_out;

    k_bnstats<<<256, 256>>>(x);
    k_fuseW<<<3, 256>>>(wk, bk, wq, bq, wv, bv, gamma, beta);
    k_gemm_kqv<<<dim3(6, 1024), 256>>>(x);
    k_kstats<<<2048, 256>>>();
    k_qstats<<<1024, 256>>>();
    k_context<<<dim3(16, 16), 256>>>();
    k_reduce_ctx<<<16, 256>>>();
    k_gate<<<1, 32>>>(w_fc1, b_fc1, w_fc2, b_fc2);
    k_combine<<<512, 256>>>(w_se);
    k_mkM<<<128, 256>>>(w_rep);
    k_bias2<<<1, 256>>>(w_rep, b_rep, b_se);
    k_final_fused<<<dim3(2, 1024), 256>>>(out);
}

// round 8
// speedup vs baseline: 2.2704x; 1.1337x over previous
#include <cuda_runtime.h>
#include <cuda_fp16.h>
#include <cstdint>

#define BATCH 8
#define CCH   256
#define SPA   16384
#define HEADS 2
#define HK    128

// ---------------- scratch ----------------
__device__ float  g_mean[CCH];
__device__ float  g_rstd[CCH];
__device__ float  g_wf[768 * 256];
__device__ float  g_bf[768];
__device__ __half g_k[BATCH * CCH * SPA];   // k logits (fp16, bias added)
__device__ __half g_q[BATCH * CCH * SPA];   // q ALREADY SOFTMAXED (fp16)
__device__ __half g_v[BATCH * CCH * SPA];
__device__ float  g_ctx_part[16 * 16 * 128 * 128];
__device__ float  g_context[16 * 128 * 128];
__device__ float  g_ctx[BATCH * 128 * 128];
__device__ float  g_pooled_part[16 * 8];
__device__ float  g_gate[16];
__device__ float  g_kpart[128 * 2048];      // per-s-tile partial exp sums
__device__ float  g_kinv[2048];
__device__ float  g_M[BATCH * 256 * 256];
__device__ float  g_b2[256];

#define CTX_SCALE      16384.0f
#define CTX_UNSCALE    (1.0f / 16384.0f)

// ---------------- helpers ----------------
__device__ __forceinline__ uint32_t pk2(float lo, float hi) {
    uint32_t r;
    asm("cvt.rn.f16x2.f32 %0, %1, %2;" : "=r"(r) : "f"(hi), "f"(lo));
    return r;
}
__device__ __forceinline__ float2 h2f(uint32_t w) {
    __half2 h = *reinterpret_cast<__half2*>(&w);
    return __half22float2(h);
}
__device__ __forceinline__ uint32_t prmt(uint32_t a, uint32_t b, uint32_t sel) {
    uint32_t r;
    asm("prmt.b32 %0, %1, %2, %3;" : "=r"(r) : "r"(a), "r"(b), "r"(sel));
    return r;
}

__device__ __forceinline__ void mma_f16(float c[4], const uint32_t a[4], const uint32_t b[2]) {
    asm volatile(
        "mma.sync.aligned.m16n8k16.row.col.f32.f16.f16.f32 "
        "{%0,%1,%2,%3}, {%4,%5,%6,%7}, {%8,%9}, {%0,%1,%2,%3};"
        : "+f"(c[0]), "+f"(c[1]), "+f"(c[2]), "+f"(c[3])
        : "r"(a[0]), "r"(a[1]), "r"(a[2]), "r"(a[3]), "r"(b[0]), "r"(b[1]));
}

#define AS_H 20
#define BS_H 136

__device__ __forceinline__ void mma_block16(const uint32_t* __restrict__ As,
                                            const uint32_t* __restrict__ Bs,
                                            int mw, int nw, int g, int tig,
                                            float (&acc)[4][4][4]) {
#pragma unroll
    for (int ks2 = 0; ks2 < 16; ks2 += 8) {
        uint32_t a[4][4], b[4][2];
#pragma unroll
        for (int i = 0; i < 4; ++i) {
            const uint32_t* A0 = As + (mw + i * 16 + g) * AS_H + ks2;
            const uint32_t* A1 = A0 + 8 * AS_H;
            a[i][0] = A0[tig];     a[i][1] = A1[tig];
            a[i][2] = A0[tig + 4]; a[i][3] = A1[tig + 4];
        }
#pragma unroll
        for (int j = 0; j < 4; ++j) {
            int cb = nw + j * 8 + g;
            b[j][0] = Bs[(ks2 + tig) * BS_H + cb];
            b[j][1] = Bs[(ks2 + tig + 4) * BS_H + cb];
        }
#pragma unroll
        for (int i = 0; i < 4; ++i)
#pragma unroll
            for (int j = 0; j < 4; ++j)
                mma_f16(acc[i][j], a[i], b[j]);
    }
}

// ---------------- K1: BatchNorm statistics ----------------
__global__ void k_bnstats(const float* __restrict__ x) {
    const int c = blockIdx.x;
    const int tid = threadIdx.x;
    float s = 0.f, s2 = 0.f;
    for (int b = 0; b < BATCH; ++b) {
        const float4* p = (const float4*)(x + ((size_t)(b * CCH + c) << 14));
        for (int i = tid; i < SPA / 4; i += 256) {
            float4 v = p[i];
            s  += v.x + v.y + v.z + v.w;
            s2 += v.x * v.x + v.y * v.y + v.z * v.z + v.w * v.w;
        }
    }
    __shared__ float sa[256], sb[256];
    sa[tid] = s; sb[tid] = s2;
    __syncthreads();
    for (int st = 128; st > 0; st >>= 1) {
        if (tid < st) { sa[tid] += sa[tid + st]; sb[tid] += sb[tid + st]; }
        __syncthreads();
    }
    if (tid == 0) {
        const float inv_n = 1.f / (float)(BATCH * SPA);
        float mean = sa[0] * inv_n;
        float var  = sb[0] * inv_n - mean * mean;
        g_mean[c] = mean;
        g_rstd[c] = rsqrtf(var + 1e-5f);
    }
}

// ---------------- K2: fold BN into kqv weights ----------------
__global__ void k_fuseW(const float* __restrict__ wk, const float* __restrict__ bk,
                        const float* __restrict__ wq, const float* __restrict__ bq,
                        const float* __restrict__ wv, const float* __restrict__ bv,
                        const float* __restrict__ gamma, const float* __restrict__ beta) {
    int o = blockIdx.x * blockDim.x + threadIdx.x;
    if (o >= 768) return;
    const float* W; const float* bias; int r;
    if (o < 256)      { W = wk; bias = bk; r = o; }
    else if (o < 512) { W = wq; bias = bq; r = o - 256; }
    else              { W = wv; bias = bv; r = o - 512; }
    float bacc = bias[r];
    for (int c = 0; c < 256; ++c) {
        float a = g_rstd[c] * gamma[c];
        float d = beta[c] - g_mean[c] * a;
        float w = W[r * 256 + c];
        g_wf[o * 256 + c] = w * a;
        bacc += w * d;
    }
    g_bf[o] = bacc;
}

// ---------------- K3: fused kqv GEMM + softmax-stats epilogue ----------------
__global__ __launch_bounds__(256) void k_gemm_kqv(const float* __restrict__ x) {
    __shared__ uint32_t As[2][128 * AS_H];
    __shared__ uint32_t Bs[2][16 * BS_H];
    const int tid = threadIdx.x;
    const int lane = tid & 31, wid = tid >> 5;
    const int g = lane >> 2, tig = lane & 3;
    const int mw = (wid & 1) * 64, nw = (wid >> 1) * 32;

    const int m0 = blockIdx.x << 7;
    const int by = blockIdx.y;
    const int b = by >> 7, s0 = (by & 127) << 7;
    const float* Bbase = x + ((size_t)b * CCH) * SPA;

    const int ar = tid >> 1, ak = (tid & 1) * 16;
    const int bkp = tid >> 4, bs = (tid & 15) * 8;

    float4 pa[4], pb[4];
    float acc[4][4][4] = {};

#define KQV_LOAD(ks) do { \
    _Pragma("unroll") \
    for (int f = 0; f < 4; ++f) \
        pa[f] = *(const float4*)(g_wf + (m0 + ar) * 256 + (ks) + ak + f * 4); \
    const float* r0_ = Bbase + (size_t)((ks) + 2 * bkp) * SPA + s0 + bs; \
    pb[0] = *(const float4*)r0_;  pb[1] = *(const float4*)(r0_ + 4); \
    pb[2] = *(const float4*)(r0_ + SPA); pb[3] = *(const float4*)(r0_ + SPA + 4); \
} while (0)

#define KQV_STAGE(buf) do { \
    uint32_t* dA = As[buf] + ar * AS_H + (ak >> 1); \
    dA[0] = pk2(pa[0].x, pa[0].y); dA[1] = pk2(pa[0].z, pa[0].w); \
    dA[2] = pk2(pa[1].x, pa[1].y); dA[3] = pk2(pa[1].z, pa[1].w); \
    dA[4] = pk2(pa[2].x, pa[2].y); dA[5] = pk2(pa[2].z, pa[2].w); \
    dA[6] = pk2(pa[3].x, pa[3].y); dA[7] = pk2(pa[3].z, pa[3].w); \
    uint32_t* dB = Bs[buf] + bkp * BS_H + bs; \
    dB[0] = pk2(pb[0].x, pb[2].x); dB[1] = pk2(pb[0].y, pb[2].y); \
    dB[2] = pk2(pb[0].z, pb[2].z); dB[3] = pk2(pb[0].w, pb[2].w); \
    dB[4] = pk2(pb[1].x, pb[3].x); dB[5] = pk2(pb[1].y, pb[3].y); \
    dB[6] = pk2(pb[1].z, pb[3].z); dB[7] = pk2(pb[1].w, pb[3].w); \
} while (0)

    KQV_LOAD(0);
    KQV_STAGE(0);
    KQV_LOAD(32);
    __syncthreads();

    for (int it = 0; it < 8; ++it) {
        const int cur = it & 1;
        if (it + 1 < 8) KQV_STAGE(cur ^ 1);
        if (it + 2 < 8) KQV_LOAD((it + 2) * 32);
        mma_block16(As[cur], Bs[cur], mw, nw, g, tig, acc);
        __syncthreads();
    }

    // ---- epilogue (smem reuse) ----
    float* red  = (float*)As;        // 128 x 16
    float* cmax = red + 2048;        // 128
    float* cinv = cmax + 128;        // 128

    if (m0 < 256) {
        // ===== k tile: write logits fp16 + per-row partial exp sums (max=0) =====
        const int slot = (wid >> 1) * 4 + tig;
#pragma unroll
        for (int i = 0; i < 4; ++i) {
            int r0 = mw + i * 16 + g;
            float b0 = g_bf[m0 + r0], b1 = g_bf[m0 + r0 + 8];
            float p0 = 0.f, p1 = 0.f;
#pragma unroll
            for (int j = 0; j < 4; ++j) {
                int col = s0 + nw + j * 8 + tig * 2;
                float v0 = acc[i][j][0] + b0, v1 = acc[i][j][1] + b0;
                float v2 = acc[i][j][2] + b1, v3 = acc[i][j][3] + b1;
                __half* o0 = g_k + (size_t)(b * CCH + m0 + r0) * SPA + col;
                *(uint32_t*)o0 = pk2(v0, v1);
                *(uint32_t*)(o0 + (size_t)8 * SPA) = pk2(v2, v3);
                p0 += __expf(v0) + __expf(v1);
                p1 += __expf(v2) + __expf(v3);
            }
            red[r0 * 16 + slot]       = p0;
            red[(r0 + 8) * 16 + slot] = p1;
        }
        __syncthreads();
        if (tid < 128) {
            float s = 0.f;
#pragma unroll
            for (int t = 0; t < 16; ++t) s += red[tid * 16 + t];
            g_kpart[(size_t)(by & 127) * 2048 + (b * 256 + m0 + tid)] = s;
        }
    } else if (m0 < 512) {
        // ===== q tile: full in-CTA column softmax (over the head's 128 channels) =====
        const int rbase = m0 - 256;
        const int slotq = (wid & 1) * 8 + g;
        // pass 1: column max
#pragma unroll
        for (int j = 0; j < 4; ++j) {
            int cl = nw + j * 8 + tig * 2;
            float mA = -1e30f, mB = -1e30f;
#pragma unroll
            for (int i = 0; i < 4; ++i) {
                float b0 = g_bf[m0 + mw + i * 16 + g];
                float b1 = g_bf[m0 + mw + i * 16 + g + 8];
                mA = fmaxf(mA, fmaxf(acc[i][j][0] + b0, acc[i][j][2] + b1));
                mB = fmaxf(mB, fmaxf(acc[i][j][1] + b0, acc[i][j][3] + b1));
            }
            red[cl * 16 + slotq]       = mA;
            red[(cl + 1) * 16 + slotq] = mB;
        }
        __syncthreads();
        if (tid < 128) {
            float m = -1e30f;
#pragma unroll
            for (int t = 0; t < 16; ++t) m = fmaxf(m, red[tid * 16 + t]);
            cmax[tid] = m;
        }
        __syncthreads();
        // pass 2: column exp-sums
#pragma unroll
        for (int j = 0; j < 4; ++j) {
            int cl = nw + j * 8 + tig * 2;
            float cmA = cmax[cl], cmB = cmax[cl + 1];
            float sA = 0.f, sB = 0.f;
#pragma unroll
            for (int i = 0; i < 4; ++i) {
                float b0 = g_bf[m0 + mw + i * 16 + g];
                float b1 = g_bf[m0 + mw + i * 16 + g + 8];
                sA += __expf(acc[i][j][0] + b0 - cmA) + __expf(acc[i][j][2] + b1 - cmA);
                sB += __expf(acc[i][j][1] + b0 - cmB) + __expf(acc[i][j][3] + b1 - cmB);
            }
            red[cl * 16 + slotq]       = sA;
            red[(cl + 1) * 16 + slotq] = sB;
        }
        __syncthreads();
        if (tid < 128) {
            float s = 0.f;
#pragma unroll
            for (int t = 0; t < 16; ++t) s += red[tid * 16 + t];
            cinv[tid] = 1.f / s;
        }
        __syncthreads();
        // pass 3: write normalized q_sm (fp16)
#pragma unroll
        for (int i = 0; i < 4; ++i) {
            int r0 = mw + i * 16 + g;
            float b0 = g_bf[m0 + r0], b1 = g_bf[m0 + r0 + 8];
#pragma unroll
            for (int j = 0; j < 4; ++j) {
                int cl = nw + j * 8 + tig * 2;
                float cmA = cmax[cl], cmB = cmax[cl + 1];
                float ciA = cinv[cl], ciB = cinv[cl + 1];
                int col = s0 + cl;
                __half* o0 = g_q + (size_t)(b * CCH + rbase + r0) * SPA + col;
                *(uint32_t*)o0 = pk2(__expf(acc[i][j][0] + b0 - cmA) * ciA,
                                     __expf(acc[i][j][1] + b0 - cmB) * ciB);
                *(uint32_t*)(o0 + (size_t)8 * SPA) =
                    pk2(__expf(acc[i][j][2] + b1 - cmA) * ciA,
                        __expf(acc[i][j][3] + b1 - cmB) * ciB);
            }
        }
    } else {
        // ===== v tile: plain bias-add store =====
        const int rbase = m0 - 512;
#pragma unroll
        for (int i = 0; i < 4; ++i) {
            int r0 = mw + i * 16 + g;
            float b0 = g_bf[m0 + r0], b1 = g_bf[m0 + r0 + 8];
#pragma unroll
            for (int j = 0; j < 4; ++j) {
                int col = s0 + nw + j * 8 + tig * 2;
                __half* o0 = g_v + (size_t)(b * CCH + rbase + r0) * SPA + col;
                *(uint32_t*)o0 = pk2(acc[i][j][0] + b0, acc[i][j][1] + b0);
                *(uint32_t*)(o0 + (size_t)8 * SPA) = pk2(acc[i][j][2] + b1, acc[i][j][3] + b1);
            }
        }
    }
}

// ---------------- K4: reduce k partial sums -> 1/sum ----------------
__global__ void k_ksum() {
    int row = blockIdx.x * 256 + threadIdx.x;   // 8 blocks x 256 = 2048
    float s = 0.f;
    for (int st = 0; st < 128; ++st) s += g_kpart[(size_t)st * 2048 + row];
    g_kinv[row] = 1.f / s;
}

// ---------------- K6: context softmax(k) @ v^T (fp16, double-buffered) -------
__global__ __launch_bounds__(256) void k_context() {
    __shared__ uint32_t As[2][128 * AS_H];
    __shared__ uint32_t Bs[2][16 * BS_H];
    const int tid = threadIdx.x;
    const int lane = tid & 31, wid = tid >> 5;
    const int g = lane >> 2, tig = lane & 3;
    const int mw = (wid & 1) * 64, nw = (wid >> 1) * 32;

    const int split = blockIdx.x;
    const int bn = blockIdx.y;
    const __half* Kb = g_k + ((size_t)bn * HK) * SPA;
    const __half* Vb = g_v + ((size_t)bn * HK) * SPA;
    const int sb0 = split * 1024;

    const int row = tid >> 1, sq = (tid & 1) * 16;
    const float kiv = g_kinv[bn * HK + row] * CTX_SCALE;

    uint4 ra0, ra1, rb0, rb1;
    float acc[4][4][4] = {};

#define CTX_LOAD(ks) do { \
    const uint4* ksrc = (const uint4*)(Kb + (size_t)row * SPA + (ks) + sq); \
    ra0 = ksrc[0]; ra1 = ksrc[1]; \
    const uint4* vsrc = (const uint4*)(Vb + (size_t)row * SPA + (ks) + sq); \
    rb0 = vsrc[0]; rb1 = vsrc[1]; \
} while (0)

#define CTX_STAGE(buf) do { \
    uint32_t* dA = As[buf] + row * AS_H + (sq >> 1); \
    const uint32_t* wa = (const uint32_t*)&ra0; \
    _Pragma("unroll") \
    for (int q = 0; q < 4; ++q) { \
        float2 f = h2f(wa[q]); \
        dA[q] = pk2(__expf(f.x) * kiv, __expf(f.y) * kiv); \
    } \
    const uint32_t* wa1 = (const uint32_t*)&ra1; \
    _Pragma("unroll") \
    for (int q = 0; q < 4; ++q) { \
        float2 f = h2f(wa1[q]); \
        dA[4 + q] = pk2(__expf(f.x) * kiv, __expf(f.y) * kiv); \
    } \
    const int rbo = sq >> 1; \
    uint32_t* BB = Bs[buf]; \
    BB[(rbo + 0) * BS_H + row] = rb0.x; BB[(rbo + 1) * BS_H + row] = rb0.y; \
    BB[(rbo + 2) * BS_H + row] = rb0.z; BB[(rbo + 3) * BS_H + row] = rb0.w; \
    BB[(rbo + 4) * BS_H + row] = rb1.x; BB[(rbo + 5) * BS_H + row] = rb1.y; \
    BB[(rbo + 6) * BS_H + row] = rb1.z; BB[(rbo + 7) * BS_H + row] = rb1.w; \
} while (0)

    CTX_LOAD(sb0);
    CTX_STAGE(0);
    CTX_LOAD(sb0 + 32);
    __syncthreads();

    for (int it = 0; it < 32; ++it) {
        const int cur = it & 1;
        if (it + 1 < 32) CTX_STAGE(cur ^ 1);
        if (it + 2 < 32) CTX_LOAD(sb0 + (it + 2) * 32);
        mma_block16(As[cur], Bs[cur], mw, nw, g, tig, acc);
        __syncthreads();
    }

    float* outp = g_ctx_part + ((size_t)(bn * 16 + split)) * 16384;
#pragma unroll
    for (int i = 0; i < 4; ++i) {
        int row0 = mw + i * 16 + g;
#pragma unroll
        for (int j = 0; j < 4; ++j) {
            int col = nw + j * 8 + tig * 2;
            float* o0 = outp + row0 * 128 + col;
            float* o1 = o0 + 8 * 128;
            *(float2*)o0 = make_float2(acc[i][j][0] * CTX_UNSCALE, acc[i][j][1] * CTX_UNSCALE);
            *(float2*)o1 = make_float2(acc[i][j][2] * CTX_UNSCALE, acc[i][j][3] * CTX_UNSCALE);
        }
    }
}

// ---------------- K7: reduce partials + pooled partials (parallel) ----------------
__global__ void k_reduce_ctx() {
    const int ch = blockIdx.x;     // 0..7
    const int bn = blockIdx.y;     // 0..15
    const int tid = threadIdx.x;
    const int e0 = ch * 2048;
    float acc = 0.f;
    for (int e = e0 + tid; e < e0 + 2048; e += 256) {
        float s = 0.f;
#pragma unroll
        for (int p = 0; p < 16; ++p)
            s += g_ctx_part[((size_t)(bn * 16 + p)) * 16384 + e];
        g_context[((size_t)bn << 14) + e] = s;
        acc += s;
    }
    __shared__ float sm[256];
    sm[tid] = acc; __syncthreads();
    for (int st = 128; st > 0; st >>= 1) {
        if (tid < st) sm[tid] += sm[tid + st];
        __syncthreads();
    }
    if (tid == 0) g_pooled_part[bn * 8 + ch] = sm[0];
}

// ---------------- K8: SE gate ----------------
__global__ void k_gate(const float* __restrict__ w_fc1, const float* __restrict__ b_fc1,
                       const float* __restrict__ w_fc2, const float* __restrict__ b_fc2) {
    int b = threadIdx.x;
    if (b >= BATCH) return;
    float p0 = 0.f, p1 = 0.f;
#pragma unroll
    for (int ch = 0; ch < 8; ++ch) {
        p0 += g_pooled_part[(b * 2) * 8 + ch];
        p1 += g_pooled_part[(b * 2 + 1) * 8 + ch];
    }
    p0 *= (1.f / 16384.f);
    p1 *= (1.f / 16384.f);
    float h0 = fmaxf(0.f, p0 * w_fc1[0] + p1 * w_fc1[1] + b_fc1[0]);
    float h1 = fmaxf(0.f, p0 * w_fc1[2] + p1 * w_fc1[3] + b_fc1[1]);
    float z0 = h0 * w_fc2[0] + h1 * w_fc2[1] + b_fc2[0];
    float z1 = h0 * w_fc2[2] + h1 * w_fc2[3] + b_fc2[1];
    g_gate[b * 2]     = 1.f / (1.f + __expf(-z0));
    g_gate[b * 2 + 1] = 1.f / (1.f + __expf(-z1));
}

// ---------------- K9: combine heads ----------------
__global__ void k_combine(const float* __restrict__ w_se) {
    int idx = blockIdx.x * 256 + threadIdx.x;
    int b = idx >> 14;
    int e = idx & 16383;
    float v = w_se[0] * g_gate[b * 2]     * g_context[((size_t)(b * 2))     * 16384 + e]
            + w_se[1] * g_gate[b * 2 + 1] * g_context[((size_t)(b * 2 + 1)) * 16384 + e];
    g_ctx[idx] = v;
}

// ---------------- K10: M_b = w_rep-slices @ ctx_b ----------------
__global__ __launch_bounds__(256) void k_mkM(const float* __restrict__ w_rep) {
    __shared__ float Ws[64][65];
    __shared__ float Cs[64][65];
    const int bid = blockIdx.x;
    const int b = bid >> 4;
    const int rem = bid & 15;
    const int ot = rem >> 2, kt = rem & 3;
    const int n = kt >> 1;
    const int kc0 = (kt & 1) << 6;
    const int o0 = ot << 6;
    const int tid = threadIdx.x;
    const int tx = tid & 15, ty = tid >> 4;
    const float* ctxb = g_ctx + (size_t)b * 16384;
    float acc[4][4] = {};
    const int lrow = tid >> 2;
    const int lc0 = (tid & 3) << 4;
    for (int h = 0; h < 2; ++h) {
        const int vb = n * 128 + h * 64;
#pragma unroll
        for (int f = 0; f < 4; ++f) {
            float4 wv = *(const float4*)(w_rep + (o0 + lrow) * 256 + vb + lc0 + f * 4);
            Ws[lrow][lc0 + f * 4 + 0] = wv.x; Ws[lrow][lc0 + f * 4 + 1] = wv.y;
            Ws[lrow][lc0 + f * 4 + 2] = wv.z; Ws[lrow][lc0 + f * 4 + 3] = wv.w;
            float4 cv = *(const float4*)(ctxb + (kc0 + lrow) * 128 + h * 64 + lc0 + f * 4);
            Cs[lrow][lc0 + f * 4 + 0] = cv.x; Cs[lrow][lc0 + f * 4 + 1] = cv.y;
            Cs[lrow][lc0 + f * 4 + 2] = cv.z; Cs[lrow][lc0 + f * 4 + 3] = cv.w;
        }
        __syncthreads();
        for (int vl = 0; vl < 64; ++vl) {
            float a[4], bb[4];
#pragma unroll
            for (int i = 0; i < 4; ++i) a[i]  = Ws[ty * 4 + i][vl];
#pragma unroll
            for (int j = 0; j < 4; ++j) bb[j] = Cs[tx * 4 + j][vl];
#pragma unroll
            for (int i = 0; i < 4; ++i)
#pragma unroll
                for (int j = 0; j < 4; ++j) acc[i][j] += a[i] * bb[j];
        }
        __syncthreads();
    }
#pragma unroll
    for (int i = 0; i < 4; ++i)
#pragma unroll
        for (int j = 0; j < 4; ++j)
            g_M[(size_t)b * 65536 + (o0 + ty * 4 + i) * 256 + kt * 64 + tx * 4 + j] = acc[i][j];
}

// ---------------- K11: b2 bias fold ----------------
__global__ void k_bias2(const float* __restrict__ w_rep, const float* __restrict__ b_rep,
                        const float* __restrict__ b_se) {
    int o = threadIdx.x;
    float s = 0.f;
    for (int c = 0; c < 256; ++c) s += w_rep[o * 256 + c];
    g_b2[o] = b_rep[o] + b_se[0] * s;
}

// ---------------- K12: fused final GEMM M_b @ q_sm + b2 (fp16, raw q) ----------
__global__ __launch_bounds__(256) void k_final_fused(float* __restrict__ out) {
    __shared__ uint32_t As[2][128 * AS_H];
    __shared__ uint32_t Bs[2][16 * BS_H];
    const int tid = threadIdx.x;
    const int lane = tid & 31, wid = tid >> 5;
    const int g = lane >> 2, tig = lane & 3;
    const int mw = (wid & 1) * 64, nw = (wid >> 1) * 32;

    const int m0 = blockIdx.x << 7;
    const int by = blockIdx.y;
    const int b = by >> 7, s0 = (by & 127) << 7;
    const float* Am = g_M + (size_t)b * 65536;
    const __half* Bq = g_q + (size_t)b * CCH * SPA;

    const int ar = tid >> 1, ak = (tid & 1) * 16;
    const int bkp = tid >> 4, bs = (tid & 15) * 8;

    float4 pa[4];
    uint4 rb0, rb1;
    float acc[4][4][4] = {};

#define FIN_LOAD(ks) do { \
    _Pragma("unroll") \
    for (int f = 0; f < 4; ++f) \
        pa[f] = *(const float4*)(Am + (m0 + ar) * 256 + (ks) + ak + f * 4); \
    const __half* q0_ = Bq + (size_t)((ks) + 2 * bkp) * SPA + s0 + bs; \
    rb0 = *(const uint4*)q0_; \
    rb1 = *(const uint4*)(q0_ + SPA); \
} while (0)

#define FIN_STAGE(buf) do { \
    uint32_t* dA = As[buf] + ar * AS_H + (ak >> 1); \
    dA[0] = pk2(pa[0].x, pa[0].y); dA[1] = pk2(pa[0].z, pa[0].w); \
    dA[2] = pk2(pa[1].x, pa[1].y); dA[3] = pk2(pa[1].z, pa[1].w); \
    dA[4] = pk2(pa[2].x, pa[2].y); dA[5] = pk2(pa[2].z, pa[2].w); \
    dA[6] = pk2(pa[3].x, pa[3].y); dA[7] = pk2(pa[3].z, pa[3].w); \
    const uint32_t* w0 = (const uint32_t*)&rb0; \
    const uint32_t* w1 = (const uint32_t*)&rb1; \
    uint32_t* dB = Bs[buf] + bkp * BS_H + bs; \
    _Pragma("unroll") \
    for (int q = 0; q < 4; ++q) { \
        dB[2 * q]     = prmt(w0[q], w1[q], 0x5410); \
        dB[2 * q + 1] = prmt(w0[q], w1[q], 0x7632); \
    } \
} while (0)

    FIN_LOAD(0);
    FIN_STAGE(0);
    FIN_LOAD(32);
    __syncthreads();

    for (int it = 0; it < 8; ++it) {
        const int cur = it & 1;
        if (it + 1 < 8) FIN_STAGE(cur ^ 1);
        if (it + 2 < 8) FIN_LOAD((it + 2) * 32);
        mma_block16(As[cur], Bs[cur], mw, nw, g, tig, acc);
        __syncthreads();
    }

#pragma unroll
    for (int i = 0; i < 4; ++i) {
        int row0 = m0 + mw + i * 16 + g;
        float bias0 = g_b2[row0];
        float bias1 = g_b2[row0 + 8];
#pragma unroll
        for (int j = 0; j < 4; ++j) {
            int col = s0 + nw + j * 8 + tig * 2;
            float* o0 = out + (size_t)(b * CCH + row0) * SPA + col;
            float* o1 = o0 + (size_t)8 * SPA;
            *(float2*)o0 = make_float2(acc[i][j][0] + bias0, acc[i][j][1] + bias0);
            *(float2*)o1 = make_float2(acc[i][j][2] + bias1, acc[i][j][3] + bias1);
        }
    }
}

// ---------------- launch ----------------
extern "C" void kernel_launch(void* const* d_in, const int* in_sizes, int n_in,
                              void* d_out, int out_size) {
    const float* x     = (const float*)d_in[0];
    const float* gamma = (const float*)d_in[1];
    const float* beta  = (const float*)d_in[2];
    const float* wk    = (const float*)d_in[3];
    const float* bk    = (const float*)d_in[4];
    const float* wq    = (const float*)d_in[5];
    const float* bq    = (const float*)d_in[6];
    const float* wv    = (const float*)d_in[7];
    const float* bv    = (const float*)d_in[8];
    const float* w_fc1 = (const float*)d_in[9];
    const float* b_fc1 = (const float*)d_in[10];
    const float* w_fc2 = (const float*)d_in[11];
    const float* b_fc2 = (const float*)d_in[12];
    const float* w_se  = (const float*)d_in[13];
    const float* b_se  = (const float*)d_in[14];
    const float* w_rep = (const float*)d_in[15];
    const float* b_rep = (const float*)d_in[16];
    float* out = (float*)d_out;

    k_bnstats<<<256, 256>>>(x);
    k_fuseW<<<3, 256>>>(wk, bk, wq, bq, wv, bv, gamma, beta);
    k_gemm_kqv<<<dim3(6, 1024), 256>>>(x);
    k_ksum<<<8, 256>>>();
    k_context<<<dim3(16, 16), 256>>>();
    k_reduce_ctx<<<dim3(8, 16), 256>>>();
    k_gate<<<1, 32>>>(w_fc1, b_fc1, w_fc2, b_fc2);
    k_combine<<<512, 256>>>(w_se);
    k_mkM<<<128, 256>>>(w_rep);
    k_bias2<<<1, 256>>>(w_rep, b_rep, b_se);
    k_final_fused<<<dim3(2, 1024), 256>>>(out);
}